// round 5
// baseline (speedup 1.0000x reference)
#include <cuda_runtime.h>
#include <cuda_fp16.h>
#include <cstdint>

// Problem constants
#define B_   4
#define T_   4096
#define C_   1024
#define HD   64
#define M_   (B_ * T_)      // 16384 rows
#define NW   192            // q(64) | k(64) | v(64) fused cols
#define WIN  128            // ALiBi window (exact to ~e^-89)

// Scratch
__device__ float g_qkv[(size_t)M_ * NW];
__device__ __align__(16) char g_wBh[16 * 24576];  // W hi fp16, per-chunk SW128 images
__device__ __align__(16) char g_wBl[16 * 24576];  // W lo fp16

// ---------------- packed f32x2 helpers ----------------
__device__ __forceinline__ unsigned long long pack2(float lo, float hi) {
    unsigned long long r;
    asm("mov.b64 %0, {%1, %2};" : "=l"(r) : "f"(lo), "f"(hi));
    return r;
}
__device__ __forceinline__ void unpack2(unsigned long long v, float& lo, float& hi) {
    asm("mov.b64 {%0, %1}, %2;" : "=f"(lo), "=f"(hi) : "l"(v));
}
__device__ __forceinline__ void ffma2(unsigned long long& d,
                                      unsigned long long a, unsigned long long b) {
    asm("fma.rn.f32x2 %0, %1, %2, %0;" : "+l"(d) : "l"(a), "l"(b));
}
__device__ __forceinline__ unsigned long long fadd2(unsigned long long a,
                                                    unsigned long long b) {
    unsigned long long r;
    asm("add.rn.f32x2 %0, %1, %2;" : "=l"(r) : "l"(a), "l"(b));
    return r;
}

// ---------------- smem / mma helpers ----------------
__device__ __forceinline__ uint32_t smem_u32(const void* p) {
    uint32_t a;
    asm("{ .reg .u64 t; cvta.to.shared.u64 t, %1; cvt.u32.u64 %0, t; }"
        : "=r"(a) : "l"(p));
    return a;
}
#define SW128(off) ((off) ^ (((off) >> 3) & 0x70))

__device__ __forceinline__ void ldsm_x4(uint32_t* r, uint32_t addr) {
    asm volatile("ldmatrix.sync.aligned.m8n8.x4.shared.b16 {%0,%1,%2,%3}, [%4];"
                 : "=r"(r[0]), "=r"(r[1]), "=r"(r[2]), "=r"(r[3]) : "r"(addr));
}
__device__ __forceinline__ void mma16816h(float* c, const uint32_t* a,
                                          const uint32_t* b) {
    asm volatile(
        "mma.sync.aligned.m16n8k16.row.col.f32.f16.f16.f32 "
        "{%0,%1,%2,%3}, {%4,%5,%6,%7}, {%8,%9}, {%0,%1,%2,%3};"
        : "+f"(c[0]), "+f"(c[1]), "+f"(c[2]), "+f"(c[3])
        : "r"(a[0]), "r"(a[1]), "r"(a[2]), "r"(a[3]), "r"(b[0]), "r"(b[1]));
}
__device__ __forceinline__ void cp_async16(uint32_t s, const void* g) {
    asm volatile("{ .reg .u64 gp; cvta.to.global.u64 gp, %1;"
                 " cp.async.cg.shared.global [%0], [gp], 16; }"
                 :: "r"(s), "l"(g) : "memory");
}
__device__ __forceinline__ uint32_t h2pack(float hi_f, float lo_f) {
    uint32_t r;   // r[15:0] = fp16(lo_f), r[31:16] = fp16(hi_f)
    asm("cvt.rn.f16x2.f32 %0, %1, %2;" : "=r"(r) : "f"(hi_f), "f"(lo_f));
    return r;
}

// ---------------------------------------------------------------------------
// Prep kernel: split W into fp16 hi/lo per-chunk SW128 images. float4 loads,
// one float4 (4 k-values, 8B per image) per thread. 192 blocks x 256 thr.
// ---------------------------------------------------------------------------
__global__ __launch_bounds__(256) void prep_w(const float* __restrict__ wq,
                                              const float* __restrict__ wk,
                                              const float* __restrict__ wv) {
    int idx = blockIdx.x * 256 + threadIdx.x;   // 0..49151
    int n = idx >> 8;
    int k4 = idx & 255;
    const float* wr = (n < 64)  ? (wq + (size_t)n * C_)
                    : (n < 128) ? (wk + (size_t)(n - 64) * C_)
                                : (wv + (size_t)(n - 128) * C_);
    float4 v = *(const float4*)(wr + k4 * 4);
    int k = k4 * 4;
    int ch = k >> 6, kk = k & 63;
    uint32_t sw = SW128((uint32_t)(n * 128 + kk * 2));
    uint2 hp;
    hp.x = h2pack(v.y, v.x);
    hp.y = h2pack(v.w, v.z);
    *(uint2*)(g_wBh + ch * 24576 + sw) = hp;
    float lx = v.x - __half2float(__float2half_rn(v.x));
    float ly = v.y - __half2float(__float2half_rn(v.y));
    float lz = v.z - __half2float(__float2half_rn(v.z));
    float lw = v.w - __half2float(__float2half_rn(v.w));
    uint2 lp;
    lp.x = h2pack(ly, lx);
    lp.y = h2pack(lw, lz);
    *(uint2*)(g_wBl + ch * 24576 + sw) = lp;
}

// ---------------------------------------------------------------------------
// Kernel 1: QKV projection via mma.sync fp16 (2-term: A*Bh + A*Bl).
// BM=128, BN=192, BK=64, 256 threads, 8 warps = 2(M) x 4(N), warp tile 64x48.
// Double-buffered smem; B via cp.async, A prefetched into registers.
// ---------------------------------------------------------------------------
#define QK_SMEM 131072

__global__ __launch_bounds__(256) void qkv_mma_kernel(const float* __restrict__ x) {
    extern __shared__ char sm[];
    const uint32_t sb = smem_u32(sm);
    const int tid = threadIdx.x;
    const int wid = tid >> 5;
    const int lane = tid & 31;
    const int rowBase = blockIdx.x * 128;

    const int wm = (wid >> 2) * 64;
    const int wn = (wid & 3) * 48;

    float acc[4][6][4];
#pragma unroll
    for (int i = 0; i < 4; i++)
#pragma unroll
        for (int j = 0; j < 6; j++)
#pragma unroll
            for (int k = 0; k < 4; k++) acc[i][j][k] = 0.0f;

    const uint32_t a_row = (uint32_t)(lane & 15);
    const uint32_t a_kb  = (uint32_t)((lane >> 4) * 16);
    const uint32_t b_n   = (uint32_t)((lane & 7) + ((lane >> 4) << 3));
    const uint32_t b_kb  = (uint32_t)(((lane >> 3) & 1) * 16);

    const int ar0 = tid >> 3;
    const int ac8 = tid & 7;

    float4 av[8];

    // ---- prologue: chunk 0 ----
    {
#pragma unroll
        for (int t = 0; t < 6; t++) {
            cp_async16(sb + 16384 + tid * 16 + t * 4096, g_wBh + tid * 16 + t * 4096);
            cp_async16(sb + 40960 + tid * 16 + t * 4096, g_wBl + tid * 16 + t * 4096);
        }
        asm volatile("cp.async.commit_group;" ::: "memory");
#pragma unroll
        for (int t = 0; t < 4; t++) {
            const float* src = x + (size_t)(rowBase + ar0 + t * 32) * C_ + ac8 * 8;
            av[2 * t] = *(const float4*)src;
            av[2 * t + 1] = *(const float4*)(src + 4);
        }
#pragma unroll
        for (int t = 0; t < 4; t++) {
            uint4 p;
            p.x = h2pack(av[2 * t].y, av[2 * t].x);
            p.y = h2pack(av[2 * t].w, av[2 * t].z);
            p.z = h2pack(av[2 * t + 1].y, av[2 * t + 1].x);
            p.w = h2pack(av[2 * t + 1].w, av[2 * t + 1].z);
            uint32_t off = (uint32_t)((ar0 + t * 32) * 128 + ac8 * 16);
            *(uint4*)(sm + SW128(off)) = p;
        }
        asm volatile("cp.async.wait_group 0;" ::: "memory");
        __syncthreads();
    }

    for (int ch = 0; ch < 16; ch++) {
        const uint32_t cb = (uint32_t)(ch & 1) * 65536;
        const uint32_t nb = (uint32_t)((ch + 1) & 1) * 65536;
        const bool more = (ch < 15);

        if (more) {
            const char* gh = g_wBh + (ch + 1) * 24576;
            const char* gl = g_wBl + (ch + 1) * 24576;
#pragma unroll
            for (int t = 0; t < 6; t++) {
                cp_async16(sb + nb + 16384 + tid * 16 + t * 4096, gh + tid * 16 + t * 4096);
                cp_async16(sb + nb + 40960 + tid * 16 + t * 4096, gl + tid * 16 + t * 4096);
            }
            asm volatile("cp.async.commit_group;" ::: "memory");
            const int k0 = (ch + 1) * 64;
#pragma unroll
            for (int t = 0; t < 4; t++) {
                const float* src = x + (size_t)(rowBase + ar0 + t * 32) * C_ + k0 + ac8 * 8;
                av[2 * t] = *(const float4*)src;
                av[2 * t + 1] = *(const float4*)(src + 4);
            }
        }

#pragma unroll
        for (int s = 0; s < 4; s++) {
            const uint32_t ks16 = (uint32_t)(s * 32);
            uint32_t bh[3][4], bl[3][4];
#pragma unroll
            for (int tn = 0; tn < 3; tn++) {
                uint32_t off = (uint32_t)((wn + tn * 16 + b_n) * 128) + ks16 + b_kb;
                ldsm_x4(bh[tn], sb + cb + 16384 + SW128(off));
                ldsm_x4(bl[tn], sb + cb + 40960 + SW128(off));
            }
            uint32_t af[4][4];
#pragma unroll
            for (int tm = 0; tm < 4; tm++) {
                uint32_t off = (uint32_t)((wm + tm * 16 + a_row) * 128) + ks16 + a_kb;
                ldsm_x4(af[tm], sb + cb + SW128(off));
            }
#pragma unroll
            for (int tm = 0; tm < 4; tm++)
#pragma unroll
                for (int tn = 0; tn < 3; tn++) {
                    mma16816h(acc[tm][tn * 2 + 0], af[tm], &bh[tn][0]);
                    mma16816h(acc[tm][tn * 2 + 1], af[tm], &bh[tn][2]);
                    mma16816h(acc[tm][tn * 2 + 0], af[tm], &bl[tn][0]);
                    mma16816h(acc[tm][tn * 2 + 1], af[tm], &bl[tn][2]);
                }
        }

        if (more) {
#pragma unroll
            for (int t = 0; t < 4; t++) {
                uint4 p;
                p.x = h2pack(av[2 * t].y, av[2 * t].x);
                p.y = h2pack(av[2 * t].w, av[2 * t].z);
                p.z = h2pack(av[2 * t + 1].y, av[2 * t + 1].x);
                p.w = h2pack(av[2 * t + 1].w, av[2 * t + 1].z);
                uint32_t off = (uint32_t)((ar0 + t * 32) * 128 + ac8 * 16);
                *(uint4*)(sm + nb + SW128(off)) = p;
            }
            asm volatile("cp.async.wait_group 0;" ::: "memory");
        }
        __syncthreads();
    }

    const int er = lane >> 2;
    const int ec = (lane & 3) * 2;
#pragma unroll
    for (int tm = 0; tm < 4; tm++) {
        int r0 = rowBase + wm + tm * 16 + er;
#pragma unroll
        for (int tn = 0; tn < 6; tn++) {
            int cc = wn + tn * 8 + ec;
            *(float2*)(g_qkv + (size_t)r0 * NW + cc) =
                make_float2(acc[tm][tn][0], acc[tm][tn][1]);
            *(float2*)(g_qkv + (size_t)(r0 + 8) * NW + cc) =
                make_float2(acc[tm][tn][2], acc[tm][tn][3]);
        }
    }
}

// ---------------------------------------------------------------------------
// Kernel 2: windowed causal attention, 4 threads/query, 32 queries/block.
// Quarter-plane smem (conflict-free LDS.128 broadcasts), double-buffered
// cp.async chunk loads, inner loop unrolled by 2 keys for chain ILP.
// ---------------------------------------------------------------------------
#define PS 1032
#define C1f 0.045084246f      // (1/32) * log2(e)
#define C2f 1.0201941f        // slope * log2(e)

__global__ __launch_bounds__(128) void attn_kernel(float* __restrict__ out) {
    __shared__ float ks[2][4 * PS];
    __shared__ float vs[2][4 * PS];

    const int b = blockIdx.y;
    const int q0 = blockIdx.x * 32;
    const int tid = threadIdx.x;
    const int qL = tid >> 2;
    const int h4 = tid & 3;
    const int i = q0 + qL;
    const int row = b * T_ + i;
    const int qF = q0 + (tid >> 5) * 8;     // warp-uniform first query

    // cp.async source/dest geometry (16 float4 per thread per chunk)
    const uint32_t ksb = smem_u32(ks);
    const uint32_t vsb = smem_u32(vs);

    // issue one chunk's loads into buffer `buf`
    auto issue_chunk = [&](int jbase, int buf) {
#pragma unroll
        for (int t = 0; t < 16; t++) {
            int idx = tid + t * 128;
            int r = idx >> 5, s5 = idx & 31;
            int isV = s5 >> 4, c4 = s5 & 15;
            int p = c4 >> 2, h = c4 & 3;
            int j = jbase + r;
            if (j < 0) j = 0;
            if (j > T_ - 1) j = T_ - 1;        // clamped, rows unused anyway
            const float* src = g_qkv + (size_t)(b * T_ + j) * NW + 64 + isV * 64 + c4 * 4;
            uint32_t dst = (isV ? vsb : ksb) +
                           (uint32_t)(buf * 4 * PS + p * PS + r * 16 + h * 4) * 4u;
            cp_async16(dst, src);
        }
        asm volatile("cp.async.commit_group;" ::: "memory");
    };

    issue_chunk(q0, 0);   // chunk c=2 (jbase = q0 - 128 + 2*64)

    unsigned long long q2[8];
    {
        const ulonglong2* qp = (const ulonglong2*)(g_qkv + (size_t)row * NW + h4 * 16);
        ulonglong2 t0 = qp[0], t1 = qp[1], t2 = qp[2], t3 = qp[3];
        q2[0] = t0.x; q2[1] = t0.y; q2[2] = t1.x; q2[3] = t1.y;
        q2[4] = t2.x; q2[5] = t2.y; q2[6] = t3.x; q2[7] = t3.y;
    }

    unsigned long long vacc[8];
#pragma unroll
    for (int h = 0; h < 8; h++) vacc[h] = 0ull;
    float ssum = 0.0f;
    float m2 = 0.0f;

    for (int c = 2; c >= 0; c--) {
        const int jbase = q0 - 128 + c * 64;
        const int buf = (2 - c) & 1;
        if (c > 0) issue_chunk(jbase - 64, buf ^ 1);
        if (c > 0) { asm volatile("cp.async.wait_group 1;" ::: "memory"); }
        else       { asm volatile("cp.async.wait_group 0;" ::: "memory"); }
        __syncthreads();

        const float* kpl = ks[buf] + h4 * PS;
        const float* vpl = vs[buf] + h4 * PS;

        int jjhi = qF + 7 - jbase;      if (jjhi > 63) jjhi = 63;
        int qlow = qF - 127;            if (qlow < 0) qlow = 0;
        int jjlo = qlow - jbase;        if (jjlo < 0) jjlo = 0;

        int jj = jjhi;
        for (; jj >= jjlo + 1; jj -= 2) {
            const int da = i - (jbase + jj);
            const int db = da + 1;

            const ulonglong2* kpa = (const ulonglong2*)(kpl + jj * 16);
            const ulonglong2* kpb = (const ulonglong2*)(kpl + (jj - 1) * 16);
            ulonglong2 ka0 = kpa[0], ka1 = kpa[1], ka2 = kpa[2], ka3 = kpa[3];
            ulonglong2 kb0 = kpb[0], kb1 = kpb[1], kb2 = kpb[2], kb3 = kpb[3];

            unsigned long long x0 = 0ull, x1 = 0ull, x2 = 0ull, x3 = 0ull;
            unsigned long long y0 = 0ull, y1 = 0ull, y2 = 0ull, y3 = 0ull;
            ffma2(x0, q2[0], ka0.x); ffma2(y0, q2[0], kb0.x);
            ffma2(x1, q2[1], ka0.y); ffma2(y1, q2[1], kb0.y);
            ffma2(x2, q2[2], ka1.x); ffma2(y2, q2[2], kb1.x);
            ffma2(x3, q2[3], ka1.y); ffma2(y3, q2[3], kb1.y);
            ffma2(x0, q2[4], ka2.x); ffma2(y0, q2[4], kb2.x);
            ffma2(x1, q2[5], ka2.y); ffma2(y1, q2[5], kb2.y);
            ffma2(x2, q2[6], ka3.x); ffma2(y2, q2[6], kb3.x);
            ffma2(x3, q2[7], ka3.y); ffma2(y3, q2[7], kb3.y);
            unsigned long long xs = fadd2(fadd2(x0, x1), fadd2(x2, x3));
            unsigned long long ys = fadd2(fadd2(y0, y1), fadd2(y2, y3));
            float xa, xb, ya, yb;
            unpack2(xs, xa, xb);
            unpack2(ys, ya, yb);
            float spa = xa + xb, spb = ya + yb;
            spa += __shfl_xor_sync(0xffffffffu, spa, 1);
            spb += __shfl_xor_sync(0xffffffffu, spb, 1);
            spa += __shfl_xor_sync(0xffffffffu, spa, 2);
            spb += __shfl_xor_sync(0xffffffffu, spb, 2);

            const bool acta = (da >= 0) && (da < WIN);
            const bool actb = (db >= 0) && (db < WIN);
            float s2a = acta ? fmaf(spa, C1f, -C2f * (float)da) : -1e30f;
            float s2b = actb ? fmaf(spb, C1f, -C2f * (float)db) : -1e30f;
            if (da == 0) m2 = s2a + 5.7708f;
            if (db == 0) m2 = s2b + 5.7708f;
            float pa = exp2f(s2a - m2);
            float pb = exp2f(s2b - m2);
            ssum += pa + pb;

            unsigned long long p2a = pack2(pa, pa);
            unsigned long long p2b = pack2(pb, pb);
            const ulonglong2* vpa = (const ulonglong2*)(vpl + jj * 16);
            const ulonglong2* vpb = (const ulonglong2*)(vpl + (jj - 1) * 16);
            ulonglong2 va0 = vpa[0], va1 = vpa[1], va2 = vpa[2], va3 = vpa[3];
            ulonglong2 vb0 = vpb[0], vb1 = vpb[1], vb2 = vpb[2], vb3 = vpb[3];
            ffma2(vacc[0], p2a, va0.x); ffma2(vacc[1], p2a, va0.y);
            ffma2(vacc[2], p2a, va1.x); ffma2(vacc[3], p2a, va1.y);
            ffma2(vacc[4], p2a, va2.x); ffma2(vacc[5], p2a, va2.y);
            ffma2(vacc[6], p2a, va3.x); ffma2(vacc[7], p2a, va3.y);
            ffma2(vacc[0], p2b, vb0.x); ffma2(vacc[1], p2b, vb0.y);
            ffma2(vacc[2], p2b, vb1.x); ffma2(vacc[3], p2b, vb1.y);
            ffma2(vacc[4], p2b, vb2.x); ffma2(vacc[5], p2b, vb2.y);
            ffma2(vacc[6], p2b, vb3.x); ffma2(vacc[7], p2b, vb3.y);
        }
        // tail (odd count)
        if (jj == jjlo) {
            const int d = i - (jbase + jj);
            const ulonglong2* kp = (const ulonglong2*)(kpl + jj * 16);
            ulonglong2 ka = kp[0], kb = kp[1], kc = kp[2], kd = kp[3];
            unsigned long long a0 = 0ull, a1 = 0ull, a2 = 0ull, a3 = 0ull;
            ffma2(a0, q2[0], ka.x); ffma2(a1, q2[1], ka.y);
            ffma2(a2, q2[2], kb.x); ffma2(a3, q2[3], kb.y);
            ffma2(a0, q2[4], kc.x); ffma2(a1, q2[5], kc.y);
            ffma2(a2, q2[6], kd.x); ffma2(a3, q2[7], kd.y);
            unsigned long long as = fadd2(fadd2(a0, a1), fadd2(a2, a3));
            float lo, hi;
            unpack2(as, lo, hi);
            float sp = lo + hi;
            sp += __shfl_xor_sync(0xffffffffu, sp, 1);
            sp += __shfl_xor_sync(0xffffffffu, sp, 2);
            const bool act = (d >= 0) && (d < WIN);
            float s2 = act ? fmaf(sp, C1f, -C2f * (float)d) : -1e30f;
            if (d == 0) m2 = s2 + 5.7708f;
            float p = exp2f(s2 - m2);
            ssum += p;
            unsigned long long p2 = pack2(p, p);
            const ulonglong2* vp = (const ulonglong2*)(vpl + jj * 16);
            ulonglong2 va = vp[0], vb = vp[1], vc = vp[2], vd = vp[3];
            ffma2(vacc[0], p2, va.x); ffma2(vacc[1], p2, va.y);
            ffma2(vacc[2], p2, vb.x); ffma2(vacc[3], p2, vb.y);
            ffma2(vacc[4], p2, vc.x); ffma2(vacc[5], p2, vc.y);
            ffma2(vacc[6], p2, vd.x); ffma2(vacc[7], p2, vd.y);
        }
        __syncthreads();   // protect buf from next iteration's issue
    }

    const float rinv = 1.0f / ssum;
    float* o = out + (size_t)row * HD + h4 * 16;
#pragma unroll
    for (int p4 = 0; p4 < 4; p4++) {
        float x0, x1, x2, x3;
        unpack2(vacc[2 * p4 + 0], x0, x1);
        unpack2(vacc[2 * p4 + 1], x2, x3);
        float4 v;
        v.x = x0 * rinv; v.y = x1 * rinv; v.z = x2 * rinv; v.w = x3 * rinv;
        *(float4*)(o + p4 * 4) = v;
    }
}

// ---------------------------------------------------------------------------
extern "C" void kernel_launch(void* const* d_in, const int* in_sizes, int n_in,
                              void* d_out, int out_size) {
    const float* x  = (const float*)d_in[0];
    const float* wq = (const float*)d_in[1];
    const float* wk = (const float*)d_in[2];
    const float* wv = (const float*)d_in[3];
    float* out = (float*)d_out;

    prep_w<<<192, 256>>>(wq, wk, wv);
    cudaFuncSetAttribute(qkv_mma_kernel,
                         cudaFuncAttributeMaxDynamicSharedMemorySize, QK_SMEM);
    qkv_mma_kernel<<<M_ / 128, 256, QK_SMEM>>>(x);
    attn_kernel<<<dim3(T_ / 32, B_), 128>>>(out);
}

// round 6
// speedup vs baseline: 1.8337x; 1.8337x over previous
#include <cuda_runtime.h>
#include <cuda_fp16.h>
#include <cstdint>

// Problem constants
#define B_   4
#define T_   4096
#define C_   1024
#define HD   64
#define M_   (B_ * T_)      // 16384 rows
#define NW   192            // q(64) | k(64) | v(64) fused cols
#define WIN  128            // ALiBi window (exact to ~e^-89)

// Scratch: fused qkv as fp16 hi/lo planes [M_][192]
__device__ __align__(16) __half g_h[(size_t)M_ * NW];
__device__ __align__(16) __half g_l[(size_t)M_ * NW];
__device__ __align__(16) char g_wBh[16 * 24576];  // W hi fp16, per-chunk SW128 images
__device__ __align__(16) char g_wBl[16 * 24576];  // W lo fp16

// ---------------- smem / mma helpers ----------------
__device__ __forceinline__ uint32_t smem_u32(const void* p) {
    uint32_t a;
    asm("{ .reg .u64 t; cvta.to.shared.u64 t, %1; cvt.u32.u64 %0, t; }"
        : "=r"(a) : "l"(p));
    return a;
}
#define SW128(off) ((off) ^ (((off) >> 3) & 0x70))

__device__ __forceinline__ void ldsm_x4(uint32_t* r, uint32_t addr) {
    asm volatile("ldmatrix.sync.aligned.m8n8.x4.shared.b16 {%0,%1,%2,%3}, [%4];"
                 : "=r"(r[0]), "=r"(r[1]), "=r"(r[2]), "=r"(r[3]) : "r"(addr));
}
__device__ __forceinline__ void ldsm_x4t(uint32_t* r, uint32_t addr) {
    asm volatile("ldmatrix.sync.aligned.m8n8.x4.trans.shared.b16 {%0,%1,%2,%3}, [%4];"
                 : "=r"(r[0]), "=r"(r[1]), "=r"(r[2]), "=r"(r[3]) : "r"(addr));
}
__device__ __forceinline__ void mma16816h(float* c, const uint32_t* a,
                                          const uint32_t* b) {
    asm volatile(
        "mma.sync.aligned.m16n8k16.row.col.f32.f16.f16.f32 "
        "{%0,%1,%2,%3}, {%4,%5,%6,%7}, {%8,%9}, {%0,%1,%2,%3};"
        : "+f"(c[0]), "+f"(c[1]), "+f"(c[2]), "+f"(c[3])
        : "r"(a[0]), "r"(a[1]), "r"(a[2]), "r"(a[3]), "r"(b[0]), "r"(b[1]));
}
__device__ __forceinline__ void cp_async16(uint32_t s, const void* g) {
    asm volatile("{ .reg .u64 gp; cvta.to.global.u64 gp, %1;"
                 " cp.async.cg.shared.global [%0], [gp], 16; }"
                 :: "r"(s), "l"(g) : "memory");
}
__device__ __forceinline__ uint32_t h2pack(float hi_f, float lo_f) {
    uint32_t r;   // r[15:0] = fp16(lo_f), r[31:16] = fp16(hi_f)
    asm("cvt.rn.f16x2.f32 %0, %1, %2;" : "=r"(r) : "f"(hi_f), "f"(lo_f));
    return r;
}
__device__ __forceinline__ float ex2(float x) {
    float r;
    asm("ex2.approx.ftz.f32 %0, %1;" : "=f"(r) : "f"(x));
    return r;
}

// ---------------------------------------------------------------------------
// Prep kernel: split W into fp16 hi/lo per-chunk SW128 images.
// ---------------------------------------------------------------------------
__global__ __launch_bounds__(256) void prep_w(const float* __restrict__ wq,
                                              const float* __restrict__ wk,
                                              const float* __restrict__ wv) {
    int idx = blockIdx.x * 256 + threadIdx.x;   // 0..49151
    int n = idx >> 8;
    int k4 = idx & 255;
    const float* wr = (n < 64)  ? (wq + (size_t)n * C_)
                    : (n < 128) ? (wk + (size_t)(n - 64) * C_)
                                : (wv + (size_t)(n - 128) * C_);
    float4 v = *(const float4*)(wr + k4 * 4);
    int k = k4 * 4;
    int ch = k >> 6, kk = k & 63;
    uint32_t sw = SW128((uint32_t)(n * 128 + kk * 2));
    uint2 hp;
    hp.x = h2pack(v.y, v.x);
    hp.y = h2pack(v.w, v.z);
    *(uint2*)(g_wBh + ch * 24576 + sw) = hp;
    float lx = v.x - __half2float(__float2half_rn(v.x));
    float ly = v.y - __half2float(__float2half_rn(v.y));
    float lz = v.z - __half2float(__float2half_rn(v.z));
    float lw = v.w - __half2float(__float2half_rn(v.w));
    uint2 lp;
    lp.x = h2pack(ly, lx);
    lp.y = h2pack(lw, lz);
    *(uint2*)(g_wBl + ch * 24576 + sw) = lp;
}

// ---------------------------------------------------------------------------
// Kernel 1: QKV projection via mma.sync fp16 (2-term: A*Bh + A*Bl).
// BM=128, BN=192, BK=64, 256 threads, 8 warps = 2(M) x 4(N), warp tile 64x48.
// Double-buffered smem; B via cp.async, A prefetched into registers.
// Epilogue stores fp16 hi/lo planes (g_h, g_l).
// ---------------------------------------------------------------------------
#define QK_SMEM 131072

__global__ __launch_bounds__(256) void qkv_mma_kernel(const float* __restrict__ x) {
    extern __shared__ char sm[];
    const uint32_t sb = smem_u32(sm);
    const int tid = threadIdx.x;
    const int wid = tid >> 5;
    const int lane = tid & 31;
    const int rowBase = blockIdx.x * 128;

    const int wm = (wid >> 2) * 64;
    const int wn = (wid & 3) * 48;

    float acc[4][6][4];
#pragma unroll
    for (int i = 0; i < 4; i++)
#pragma unroll
        for (int j = 0; j < 6; j++)
#pragma unroll
            for (int k = 0; k < 4; k++) acc[i][j][k] = 0.0f;

    const uint32_t a_row = (uint32_t)(lane & 15);
    const uint32_t a_kb  = (uint32_t)((lane >> 4) * 16);
    const uint32_t b_n   = (uint32_t)((lane & 7) + ((lane >> 4) << 3));
    const uint32_t b_kb  = (uint32_t)(((lane >> 3) & 1) * 16);

    const int ar0 = tid >> 3;
    const int ac8 = tid & 7;

    float4 av[8];

    // ---- prologue: chunk 0 ----
    {
#pragma unroll
        for (int t = 0; t < 6; t++) {
            cp_async16(sb + 16384 + tid * 16 + t * 4096, g_wBh + tid * 16 + t * 4096);
            cp_async16(sb + 40960 + tid * 16 + t * 4096, g_wBl + tid * 16 + t * 4096);
        }
        asm volatile("cp.async.commit_group;" ::: "memory");
#pragma unroll
        for (int t = 0; t < 4; t++) {
            const float* src = x + (size_t)(rowBase + ar0 + t * 32) * C_ + ac8 * 8;
            av[2 * t] = *(const float4*)src;
            av[2 * t + 1] = *(const float4*)(src + 4);
        }
#pragma unroll
        for (int t = 0; t < 4; t++) {
            uint4 p;
            p.x = h2pack(av[2 * t].y, av[2 * t].x);
            p.y = h2pack(av[2 * t].w, av[2 * t].z);
            p.z = h2pack(av[2 * t + 1].y, av[2 * t + 1].x);
            p.w = h2pack(av[2 * t + 1].w, av[2 * t + 1].z);
            uint32_t off = (uint32_t)((ar0 + t * 32) * 128 + ac8 * 16);
            *(uint4*)(sm + SW128(off)) = p;
        }
        asm volatile("cp.async.wait_group 0;" ::: "memory");
        __syncthreads();
    }

    for (int ch = 0; ch < 16; ch++) {
        const uint32_t cb = (uint32_t)(ch & 1) * 65536;
        const uint32_t nb = (uint32_t)((ch + 1) & 1) * 65536;
        const bool more = (ch < 15);

        if (more) {
            const char* gh = g_wBh + (ch + 1) * 24576;
            const char* gl = g_wBl + (ch + 1) * 24576;
#pragma unroll
            for (int t = 0; t < 6; t++) {
                cp_async16(sb + nb + 16384 + tid * 16 + t * 4096, gh + tid * 16 + t * 4096);
                cp_async16(sb + nb + 40960 + tid * 16 + t * 4096, gl + tid * 16 + t * 4096);
            }
            asm volatile("cp.async.commit_group;" ::: "memory");
            const int k0 = (ch + 1) * 64;
#pragma unroll
            for (int t = 0; t < 4; t++) {
                const float* src = x + (size_t)(rowBase + ar0 + t * 32) * C_ + k0 + ac8 * 8;
                av[2 * t] = *(const float4*)src;
                av[2 * t + 1] = *(const float4*)(src + 4);
            }
        }

#pragma unroll
        for (int s = 0; s < 4; s++) {
            const uint32_t ks16 = (uint32_t)(s * 32);
            uint32_t bh[3][4], bl[3][4];
#pragma unroll
            for (int tn = 0; tn < 3; tn++) {
                uint32_t off = (uint32_t)((wn + tn * 16 + b_n) * 128) + ks16 + b_kb;
                ldsm_x4(bh[tn], sb + cb + 16384 + SW128(off));
                ldsm_x4(bl[tn], sb + cb + 40960 + SW128(off));
            }
            uint32_t af[4][4];
#pragma unroll
            for (int tm = 0; tm < 4; tm++) {
                uint32_t off = (uint32_t)((wm + tm * 16 + a_row) * 128) + ks16 + a_kb;
                ldsm_x4(af[tm], sb + cb + SW128(off));
            }
#pragma unroll
            for (int tm = 0; tm < 4; tm++)
#pragma unroll
                for (int tn = 0; tn < 3; tn++) {
                    mma16816h(acc[tm][tn * 2 + 0], af[tm], &bh[tn][0]);
                    mma16816h(acc[tm][tn * 2 + 1], af[tm], &bh[tn][2]);
                    mma16816h(acc[tm][tn * 2 + 0], af[tm], &bl[tn][0]);
                    mma16816h(acc[tm][tn * 2 + 1], af[tm], &bl[tn][2]);
                }
        }

        if (more) {
#pragma unroll
            for (int t = 0; t < 4; t++) {
                uint4 p;
                p.x = h2pack(av[2 * t].y, av[2 * t].x);
                p.y = h2pack(av[2 * t].w, av[2 * t].z);
                p.z = h2pack(av[2 * t + 1].y, av[2 * t + 1].x);
                p.w = h2pack(av[2 * t + 1].w, av[2 * t + 1].z);
                uint32_t off = (uint32_t)((ar0 + t * 32) * 128 + ac8 * 16);
                *(uint4*)(sm + nb + SW128(off)) = p;
            }
            asm volatile("cp.async.wait_group 0;" ::: "memory");
        }
        __syncthreads();
    }

    // Epilogue: store fp16 hi + lo planes
    const int er = lane >> 2;
    const int ec = (lane & 3) * 2;
#pragma unroll
    for (int tm = 0; tm < 4; tm++) {
        int r0 = rowBase + wm + tm * 16 + er;
#pragma unroll
        for (int tn = 0; tn < 6; tn++) {
            int cc = wn + tn * 8 + ec;
            float a0 = acc[tm][tn][0], a1 = acc[tm][tn][1];
            float a2 = acc[tm][tn][2], a3 = acc[tm][tn][3];
            uint32_t h01 = h2pack(a1, a0);
            uint32_t h23 = h2pack(a3, a2);
            __half2 hh01 = *reinterpret_cast<__half2*>(&h01);
            __half2 hh23 = *reinterpret_cast<__half2*>(&h23);
            uint32_t l01 = h2pack(a1 - __high2float(hh01), a0 - __low2float(hh01));
            uint32_t l23 = h2pack(a3 - __high2float(hh23), a2 - __low2float(hh23));
            *(uint32_t*)(g_h + (size_t)r0 * NW + cc) = h01;
            *(uint32_t*)(g_l + (size_t)r0 * NW + cc) = l01;
            *(uint32_t*)(g_h + (size_t)(r0 + 8) * NW + cc) = h23;
            *(uint32_t*)(g_l + (size_t)(r0 + 8) * NW + cc) = l23;
        }
    }
}

// ---------------------------------------------------------------------------
// Kernel 2: banded tensor-core attention.
// Block = 128 threads (4 warps) = 64 queries; key band [q0-128, q0+63] (192).
// Warp w owns queries 16w..16w+15 and its 9 diagonal k16 groups G = w..w+8
// (covers keys 16w..16w+143 = exactly each row's 128-window).
// S via mma fp16 (Q,K hi-only); mask+ALiBi+ex2 in frags (no max needed);
// PV via 3-term hi/lo fp16 mma, C-frag -> A-frag reuse.
// ---------------------------------------------------------------------------
#define ATT_Q  0
#define ATT_K  8192
#define ATT_VH 32768
#define ATT_VL 57344
#define ATT_SMEM 81920
#define C1f 0.045084246f      // (1/32) * log2(e)
#define C2f 1.0201941f        // slope * log2(e)

__global__ __launch_bounds__(128) void attn_kernel(float* __restrict__ out) {
    extern __shared__ char sm[];
    const uint32_t sb = smem_u32(sm);
    const int b = blockIdx.y;
    const int q0 = blockIdx.x * 64;
    const int tid = threadIdx.x;
    const int w = tid >> 5;
    const int lane = tid & 31;

    // ---- async fill: group A = Q(512) + K(1536) granules, group B = V(3072)
#pragma unroll
    for (int t = 0; t < 16; t++) {
        int idx = tid + t * 128;
        const __half* src;
        uint32_t dst;
        if (idx < 512) {
            int qr = idx >> 3, c = idx & 7;
            src = g_h + (size_t)(b * T_ + q0 + qr) * NW + c * 8;
            dst = sb + ATT_Q + SW128((uint32_t)(qr * 128 + c * 16));
        } else {
            int i2 = idx - 512;
            int r = i2 >> 3, c = i2 & 7;
            int j = q0 - 128 + r;
            if (j < 0) j = 0;
            src = g_h + (size_t)(b * T_ + j) * NW + 64 + c * 8;
            dst = sb + ATT_K + SW128((uint32_t)(r * 128 + c * 16));
        }
        cp_async16(dst, src);
    }
    asm volatile("cp.async.commit_group;" ::: "memory");
#pragma unroll
    for (int t = 0; t < 24; t++) {
        int idx = tid + t * 128;
        int isL = (idx >= 1536);
        int i2 = isL ? idx - 1536 : idx;
        int r = i2 >> 3, c = i2 & 7;
        int j = q0 - 128 + r;
        if (j < 0) j = 0;
        const __half* src = (isL ? g_l : g_h) + (size_t)(b * T_ + j) * NW + 128 + c * 8;
        uint32_t dst = sb + (isL ? ATT_VL : ATT_VH) + SW128((uint32_t)(r * 128 + c * 16));
        cp_async16(dst, src);
    }
    asm volatile("cp.async.commit_group;" ::: "memory");
    asm volatile("cp.async.wait_group 1;" ::: "memory");
    __syncthreads();

    // ---- S = Q K^T over the warp's 9 diagonal groups
    const uint32_t a_row = (uint32_t)(lane & 15);
    const uint32_t a_kb  = (uint32_t)((lane >> 4) * 16);
    const uint32_t b_n   = (uint32_t)((lane & 7) + ((lane >> 4) << 3));
    const uint32_t b_kb  = (uint32_t)(((lane >> 3) & 1) * 16);

    uint32_t af[4][4];
#pragma unroll
    for (int s = 0; s < 4; s++)
        ldsm_x4(af[s], sb + ATT_Q +
                SW128((uint32_t)((w * 16 + a_row) * 128 + s * 32) + a_kb));

    float c[18][4];
#pragma unroll
    for (int j = 0; j < 18; j++)
#pragma unroll
        for (int k = 0; k < 4; k++) c[j][k] = 0.0f;

#pragma unroll
    for (int G = 0; G < 9; G++) {
        const int grow = (w + G) * 16;
#pragma unroll
        for (int s = 0; s < 4; s++) {
            uint32_t bk[4];
            ldsm_x4(bk, sb + ATT_K +
                    SW128((uint32_t)((grow + b_n) * 128 + s * 32) + b_kb));
            mma16816h(c[2 * G], af[s], &bk[0]);
            mma16816h(c[2 * G + 1], af[s], &bk[2]);
        }
    }

    // ---- mask + ALiBi + exp2, row sums
    const int g = lane >> 2;
    const int tc2 = (lane & 3) * 2;
    float rs0 = 0.0f, rs1 = 0.0f;
#pragma unroll
    for (int jt = 0; jt < 18; jt++) {
        int nb = 16 * w + 8 * jt + tc2;           // global key-col for e=0
        int j0 = q0 - 128 + nb;                   // key index e=0 (e=1 -> j0+1)
        int d0 = g + 128 - 8 * jt - tc2;          // row g, e=0 (w cancels)
        int d1 = d0 - 1, d2 = d0 + 8, d3 = d0 + 7;
        float p0 = ex2(fmaf(c[jt][0], C1f, -(float)d0 * C2f));
        float p1 = ex2(fmaf(c[jt][1], C1f, -(float)d1 * C2f));
        float p2 = ex2(fmaf(c[jt][2], C1f, -(float)d2 * C2f));
        float p3 = ex2(fmaf(c[jt][3], C1f, -(float)d3 * C2f));
        p0 = (d0 >= 0 && d0 < WIN && j0 >= 0) ? p0 : 0.0f;
        p1 = (d1 >= 0 && d1 < WIN && j0 + 1 >= 0) ? p1 : 0.0f;
        p2 = (d2 >= 0 && d2 < WIN && j0 >= 0) ? p2 : 0.0f;
        p3 = (d3 >= 0 && d3 < WIN && j0 + 1 >= 0) ? p3 : 0.0f;
        c[jt][0] = p0; c[jt][1] = p1; c[jt][2] = p2; c[jt][3] = p3;
        rs0 += p0 + p1;
        rs1 += p2 + p3;
    }
    rs0 += __shfl_xor_sync(0xffffffffu, rs0, 1);
    rs1 += __shfl_xor_sync(0xffffffffu, rs1, 1);
    rs0 += __shfl_xor_sync(0xffffffffu, rs0, 2);
    rs1 += __shfl_xor_sync(0xffffffffu, rs1, 2);
    const float rinv0 = 1.0f / rs0;
    const float rinv1 = 1.0f / rs1;

    asm volatile("cp.async.wait_group 0;" ::: "memory");
    __syncthreads();

    // ---- PV: 3-term hi/lo over the 9 diagonal k16 steps
    float o[8][4];
#pragma unroll
    for (int j = 0; j < 8; j++)
#pragma unroll
        for (int k = 0; k < 4; k++) o[j][k] = 0.0f;

    const uint32_t vrow = (uint32_t)((lane & 7) + 8 * ((lane >> 3) & 1));
    const uint32_t vcb  = (uint32_t)(16 * (lane >> 4));

#pragma unroll
    for (int ss = 0; ss < 9; ss++) {
        const int s = w + ss;
        uint32_t aph[4], apl[4];
        aph[0] = h2pack(c[2 * ss][1], c[2 * ss][0]);
        aph[1] = h2pack(c[2 * ss][3], c[2 * ss][2]);
        aph[2] = h2pack(c[2 * ss + 1][1], c[2 * ss + 1][0]);
        aph[3] = h2pack(c[2 * ss + 1][3], c[2 * ss + 1][2]);
        {
            __half2 h0 = *reinterpret_cast<__half2*>(&aph[0]);
            __half2 h1 = *reinterpret_cast<__half2*>(&aph[1]);
            __half2 h2v = *reinterpret_cast<__half2*>(&aph[2]);
            __half2 h3 = *reinterpret_cast<__half2*>(&aph[3]);
            apl[0] = h2pack(c[2 * ss][1] - __high2float(h0),
                            c[2 * ss][0] - __low2float(h0));
            apl[1] = h2pack(c[2 * ss][3] - __high2float(h1),
                            c[2 * ss][2] - __low2float(h1));
            apl[2] = h2pack(c[2 * ss + 1][1] - __high2float(h2v),
                            c[2 * ss + 1][0] - __low2float(h2v));
            apl[3] = h2pack(c[2 * ss + 1][3] - __high2float(h3),
                            c[2 * ss + 1][2] - __low2float(h3));
        }
#pragma unroll
        for (int H = 0; H < 4; H++) {
            uint32_t ro = SW128((uint32_t)((16 * s + vrow) * 128 + 32 * H) + vcb);
            uint32_t vh[4], vl[4];
            ldsm_x4t(vh, sb + ATT_VH + ro);
            ldsm_x4t(vl, sb + ATT_VL + ro);
            mma16816h(o[2 * H], aph, &vh[0]);
            mma16816h(o[2 * H + 1], aph, &vh[2]);
            mma16816h(o[2 * H], aph, &vl[0]);
            mma16816h(o[2 * H + 1], aph, &vl[2]);
            mma16816h(o[2 * H], apl, &vh[0]);
            mma16816h(o[2 * H + 1], apl, &vh[2]);
        }
    }

    // ---- epilogue: normalize and store
    const int r0 = b * T_ + q0 + 16 * w + g;
#pragma unroll
    for (int j = 0; j < 8; j++) {
        *(float2*)(out + (size_t)r0 * HD + 8 * j + tc2) =
            make_float2(o[j][0] * rinv0, o[j][1] * rinv0);
        *(float2*)(out + (size_t)(r0 + 8) * HD + 8 * j + tc2) =
            make_float2(o[j][2] * rinv1, o[j][3] * rinv1);
    }
}

// ---------------------------------------------------------------------------
extern "C" void kernel_launch(void* const* d_in, const int* in_sizes, int n_in,
                              void* d_out, int out_size) {
    const float* x  = (const float*)d_in[0];
    const float* wq = (const float*)d_in[1];
    const float* wk = (const float*)d_in[2];
    const float* wv = (const float*)d_in[3];
    float* out = (float*)d_out;

    prep_w<<<192, 256>>>(wq, wk, wv);
    cudaFuncSetAttribute(qkv_mma_kernel,
                         cudaFuncAttributeMaxDynamicSharedMemorySize, QK_SMEM);
    qkv_mma_kernel<<<M_ / 128, 256, QK_SMEM>>>(x);
    cudaFuncSetAttribute(attn_kernel,
                         cudaFuncAttributeMaxDynamicSharedMemorySize, ATT_SMEM);
    attn_kernel<<<dim3(T_ / 64, B_), 128, ATT_SMEM>>>(out);
}

// round 8
// speedup vs baseline: 2.4677x; 1.3457x over previous
#include <cuda_runtime.h>
#include <cuda_fp16.h>
#include <cstdint>

// Problem constants
#define B_   4
#define T_   4096
#define C_   1024
#define HD   64
#define M_   (B_ * T_)      // 16384 rows
#define NW   192            // q(64) | k(64) | v(64) fused cols
#define WIN  128            // ALiBi window (exact to ~e^-89)

// Scratch: fused qkv as fp16 hi/lo planes [M_][192]
__device__ __align__(16) __half g_h[(size_t)M_ * NW];
__device__ __align__(16) __half g_l[(size_t)M_ * NW];
__device__ __align__(16) char g_wBh[16 * 24576];  // W fp16, per-chunk SW128 images

// ---------------- smem / mma helpers ----------------
__device__ __forceinline__ uint32_t smem_u32(const void* p) {
    uint32_t a;
    asm("{ .reg .u64 t; cvta.to.shared.u64 t, %1; cvt.u32.u64 %0, t; }"
        : "=r"(a) : "l"(p));
    return a;
}
#define SW128(off) ((off) ^ (((off) >> 3) & 0x70))

__device__ __forceinline__ void ldsm_x4(uint32_t* r, uint32_t addr) {
    asm volatile("ldmatrix.sync.aligned.m8n8.x4.shared.b16 {%0,%1,%2,%3}, [%4];"
                 : "=r"(r[0]), "=r"(r[1]), "=r"(r[2]), "=r"(r[3]) : "r"(addr));
}
__device__ __forceinline__ void ldsm_x4t(uint32_t* r, uint32_t addr) {
    asm volatile("ldmatrix.sync.aligned.m8n8.x4.trans.shared.b16 {%0,%1,%2,%3}, [%4];"
                 : "=r"(r[0]), "=r"(r[1]), "=r"(r[2]), "=r"(r[3]) : "r"(addr));
}
__device__ __forceinline__ void mma16816h(float* c, const uint32_t* a,
                                          const uint32_t* b) {
    asm volatile(
        "mma.sync.aligned.m16n8k16.row.col.f32.f16.f16.f32 "
        "{%0,%1,%2,%3}, {%4,%5,%6,%7}, {%8,%9}, {%0,%1,%2,%3};"
        : "+f"(c[0]), "+f"(c[1]), "+f"(c[2]), "+f"(c[3])
        : "r"(a[0]), "r"(a[1]), "r"(a[2]), "r"(a[3]), "r"(b[0]), "r"(b[1]));
}
__device__ __forceinline__ void cp_async16(uint32_t s, const void* g) {
    asm volatile("{ .reg .u64 gp; cvta.to.global.u64 gp, %1;"
                 " cp.async.cg.shared.global [%0], [gp], 16; }"
                 :: "r"(s), "l"(g) : "memory");
}
__device__ __forceinline__ uint32_t h2pack(float hi_f, float lo_f) {
    uint32_t r;   // r[15:0] = fp16(lo_f), r[31:16] = fp16(hi_f)
    asm("cvt.rn.f16x2.f32 %0, %1, %2;" : "=r"(r) : "f"(hi_f), "f"(lo_f));
    return r;
}
__device__ __forceinline__ float ex2(float x) {
    float r;
    asm("ex2.approx.ftz.f32 %0, %1;" : "=f"(r) : "f"(x));
    return r;
}

// ---------------------------------------------------------------------------
// Prep kernel: round W to fp16, stored as per-chunk SW128 images.
// ---------------------------------------------------------------------------
__global__ __launch_bounds__(256) void prep_w(const float* __restrict__ wq,
                                              const float* __restrict__ wk,
                                              const float* __restrict__ wv) {
    int idx = blockIdx.x * 256 + threadIdx.x;   // 0..49151
    int n = idx >> 8;
    int k4 = idx & 255;
    const float* wr = (n < 64)  ? (wq + (size_t)n * C_)
                    : (n < 128) ? (wk + (size_t)(n - 64) * C_)
                                : (wv + (size_t)(n - 128) * C_);
    float4 v = *(const float4*)(wr + k4 * 4);
    int k = k4 * 4;
    int ch = k >> 6, kk = k & 63;
    uint32_t sw = SW128((uint32_t)(n * 128 + kk * 2));
    uint2 hp;
    hp.x = h2pack(v.y, v.x);
    hp.y = h2pack(v.w, v.z);
    *(uint2*)(g_wBh + ch * 24576 + sw) = hp;
}

// ---------------------------------------------------------------------------
// Kernel 1: QKV projection via mma.sync fp16 (single-term W).
// BM=128, BN=192, BK=64, 256 threads, 8 warps = 2(M) x 4(N), warp tile 64x48.
// Double-buffered smem; B via cp.async, A prefetched into registers.
// Epilogue stores fp16 hi/lo planes (g_h, g_l).
// Buffer layout (per buf, 40KB): A fp16 @0 (16KB), Bh @16384 (24KB).
// ---------------------------------------------------------------------------
#define QK_BUF 40960
#define QK_SMEM (2 * QK_BUF)

__global__ __launch_bounds__(256) void qkv_mma_kernel(const float* __restrict__ x) {
    extern __shared__ char sm[];
    const uint32_t sb = smem_u32(sm);
    const int tid = threadIdx.x;
    const int wid = tid >> 5;
    const int lane = tid & 31;
    const int rowBase = blockIdx.x * 128;

    const int wm = (wid >> 2) * 64;
    const int wn = (wid & 3) * 48;

    float acc[4][6][4];
#pragma unroll
    for (int i = 0; i < 4; i++)
#pragma unroll
        for (int j = 0; j < 6; j++)
#pragma unroll
            for (int k = 0; k < 4; k++) acc[i][j][k] = 0.0f;

    const uint32_t a_row = (uint32_t)(lane & 15);
    const uint32_t a_kb  = (uint32_t)((lane >> 4) * 16);
    const uint32_t b_n   = (uint32_t)((lane & 7) + ((lane >> 4) << 3));
    const uint32_t b_kb  = (uint32_t)(((lane >> 3) & 1) * 16);

    const int ar0 = tid >> 3;
    const int ac8 = tid & 7;

    float4 av[8];

    // ---- prologue: chunk 0 ----
    {
#pragma unroll
        for (int t = 0; t < 6; t++)
            cp_async16(sb + 16384 + tid * 16 + t * 4096, g_wBh + tid * 16 + t * 4096);
        asm volatile("cp.async.commit_group;" ::: "memory");
#pragma unroll
        for (int t = 0; t < 4; t++) {
            const float* src = x + (size_t)(rowBase + ar0 + t * 32) * C_ + ac8 * 8;
            av[2 * t] = *(const float4*)src;
            av[2 * t + 1] = *(const float4*)(src + 4);
        }
#pragma unroll
        for (int t = 0; t < 4; t++) {
            uint4 p;
            p.x = h2pack(av[2 * t].y, av[2 * t].x);
            p.y = h2pack(av[2 * t].w, av[2 * t].z);
            p.z = h2pack(av[2 * t + 1].y, av[2 * t + 1].x);
            p.w = h2pack(av[2 * t + 1].w, av[2 * t + 1].z);
            uint32_t off = (uint32_t)((ar0 + t * 32) * 128 + ac8 * 16);
            *(uint4*)(sm + SW128(off)) = p;
        }
        asm volatile("cp.async.wait_group 0;" ::: "memory");
        __syncthreads();
    }

    for (int ch = 0; ch < 16; ch++) {
        const uint32_t cb = (uint32_t)(ch & 1) * QK_BUF;
        const uint32_t nb = (uint32_t)((ch + 1) & 1) * QK_BUF;
        const bool more = (ch < 15);

        if (more) {
            const char* gh = g_wBh + (ch + 1) * 24576;
#pragma unroll
            for (int t = 0; t < 6; t++)
                cp_async16(sb + nb + 16384 + tid * 16 + t * 4096, gh + tid * 16 + t * 4096);
            asm volatile("cp.async.commit_group;" ::: "memory");
            const int k0 = (ch + 1) * 64;
#pragma unroll
            for (int t = 0; t < 4; t++) {
                const float* src = x + (size_t)(rowBase + ar0 + t * 32) * C_ + k0 + ac8 * 8;
                av[2 * t] = *(const float4*)src;
                av[2 * t + 1] = *(const float4*)(src + 4);
            }
        }

#pragma unroll
        for (int s = 0; s < 4; s++) {
            const uint32_t ks16 = (uint32_t)(s * 32);
            uint32_t bh[3][4];
#pragma unroll
            for (int tn = 0; tn < 3; tn++) {
                uint32_t off = (uint32_t)((wn + tn * 16 + b_n) * 128) + ks16 + b_kb;
                ldsm_x4(bh[tn], sb + cb + 16384 + SW128(off));
            }
            uint32_t af[4][4];
#pragma unroll
            for (int tm = 0; tm < 4; tm++) {
                uint32_t off = (uint32_t)((wm + tm * 16 + a_row) * 128) + ks16 + a_kb;
                ldsm_x4(af[tm], sb + cb + SW128(off));
            }
#pragma unroll
            for (int tm = 0; tm < 4; tm++)
#pragma unroll
                for (int tn = 0; tn < 3; tn++) {
                    mma16816h(acc[tm][tn * 2 + 0], af[tm], &bh[tn][0]);
                    mma16816h(acc[tm][tn * 2 + 1], af[tm], &bh[tn][2]);
                }
        }

        if (more) {
#pragma unroll
            for (int t = 0; t < 4; t++) {
                uint4 p;
                p.x = h2pack(av[2 * t].y, av[2 * t].x);
                p.y = h2pack(av[2 * t].w, av[2 * t].z);
                p.z = h2pack(av[2 * t + 1].y, av[2 * t + 1].x);
                p.w = h2pack(av[2 * t + 1].w, av[2 * t + 1].z);
                uint32_t off = (uint32_t)((ar0 + t * 32) * 128 + ac8 * 16);
                *(uint4*)(sm + nb + SW128(off)) = p;
            }
            asm volatile("cp.async.wait_group 0;" ::: "memory");
        }
        __syncthreads();
    }

    // Epilogue: store fp16 hi + lo planes
    const int er = lane >> 2;
    const int ec = (lane & 3) * 2;
#pragma unroll
    for (int tm = 0; tm < 4; tm++) {
        int r0 = rowBase + wm + tm * 16 + er;
#pragma unroll
        for (int tn = 0; tn < 6; tn++) {
            int cc = wn + tn * 8 + ec;
            float a0 = acc[tm][tn][0], a1 = acc[tm][tn][1];
            float a2 = acc[tm][tn][2], a3 = acc[tm][tn][3];
            uint32_t h01 = h2pack(a1, a0);
            uint32_t h23 = h2pack(a3, a2);
            __half2 hh01 = *reinterpret_cast<__half2*>(&h01);
            __half2 hh23 = *reinterpret_cast<__half2*>(&h23);
            uint32_t l01 = h2pack(a1 - __high2float(hh01), a0 - __low2float(hh01));
            uint32_t l23 = h2pack(a3 - __high2float(hh23), a2 - __low2float(hh23));
            *(uint32_t*)(g_h + (size_t)r0 * NW + cc) = h01;
            *(uint32_t*)(g_l + (size_t)r0 * NW + cc) = l01;
            *(uint32_t*)(g_h + (size_t)(r0 + 8) * NW + cc) = h23;
            *(uint32_t*)(g_l + (size_t)(r0 + 8) * NW + cc) = l23;
        }
    }
}

// ---------------------------------------------------------------------------
// Kernel 2: banded tensor-core attention.
// Block = 128 threads (4 warps) = 64 queries; key band [q0-128, q0+63] (192).
// Warp w owns queries 16w..16w+15 and its 9 diagonal k16 groups G = w..w+8
// (covers keys 16w..16w+143 = exactly each row's 128-window).
// S via mma fp16 (Q,K hi-only); mask+ALiBi+ex2 in frags (no max needed);
// PV via 3-term hi/lo fp16 mma, C-frag -> A-frag reuse.
// ---------------------------------------------------------------------------
#define ATT_Q  0
#define ATT_K  8192
#define ATT_VH 32768
#define ATT_VL 57344
#define ATT_SMEM 81920
#define C1f 0.045084246f      // (1/32) * log2(e)
#define C2f 1.0201941f        // slope * log2(e)

__global__ __launch_bounds__(128) void attn_kernel(float* __restrict__ out) {
    extern __shared__ char sm[];
    const uint32_t sb = smem_u32(sm);
    const int b = blockIdx.y;
    const int q0 = blockIdx.x * 64;
    const int tid = threadIdx.x;
    const int w = tid >> 5;
    const int lane = tid & 31;

    // ---- async fill: group A = Q(512) + K(1536) granules, group B = V(3072)
#pragma unroll
    for (int t = 0; t < 16; t++) {
        int idx = tid + t * 128;
        const __half* src;
        uint32_t dst;
        if (idx < 512) {
            int qr = idx >> 3, c = idx & 7;
            src = g_h + (size_t)(b * T_ + q0 + qr) * NW + c * 8;
            dst = sb + ATT_Q + SW128((uint32_t)(qr * 128 + c * 16));
        } else {
            int i2 = idx - 512;
            int r = i2 >> 3, c = i2 & 7;
            int j = q0 - 128 + r;
            if (j < 0) j = 0;
            src = g_h + (size_t)(b * T_ + j) * NW + 64 + c * 8;
            dst = sb + ATT_K + SW128((uint32_t)(r * 128 + c * 16));
        }
        cp_async16(dst, src);
    }
    asm volatile("cp.async.commit_group;" ::: "memory");
#pragma unroll
    for (int t = 0; t < 24; t++) {
        int idx = tid + t * 128;
        int isL = (idx >= 1536);
        int i2 = isL ? idx - 1536 : idx;
        int r = i2 >> 3, c = i2 & 7;
        int j = q0 - 128 + r;
        if (j < 0) j = 0;
        const __half* src = (isL ? g_l : g_h) + (size_t)(b * T_ + j) * NW + 128 + c * 8;
        uint32_t dst = sb + (isL ? ATT_VL : ATT_VH) + SW128((uint32_t)(r * 128 + c * 16));
        cp_async16(dst, src);
    }
    asm volatile("cp.async.commit_group;" ::: "memory");
    asm volatile("cp.async.wait_group 1;" ::: "memory");
    __syncthreads();

    // ---- S = Q K^T over the warp's 9 diagonal groups
    const uint32_t a_row = (uint32_t)(lane & 15);
    const uint32_t a_kb  = (uint32_t)((lane >> 4) * 16);
    const uint32_t b_n   = (uint32_t)((lane & 7) + ((lane >> 4) << 3));
    const uint32_t b_kb  = (uint32_t)(((lane >> 3) & 1) * 16);

    uint32_t af[4][4];
#pragma unroll
    for (int s = 0; s < 4; s++)
        ldsm_x4(af[s], sb + ATT_Q +
                SW128((uint32_t)((w * 16 + a_row) * 128 + s * 32) + a_kb));

    float c[18][4];
#pragma unroll
    for (int j = 0; j < 18; j++)
#pragma unroll
        for (int k = 0; k < 4; k++) c[j][k] = 0.0f;

#pragma unroll
    for (int G = 0; G < 9; G++) {
        const int grow = (w + G) * 16;
#pragma unroll
        for (int s = 0; s < 4; s++) {
            uint32_t bk[4];
            ldsm_x4(bk, sb + ATT_K +
                    SW128((uint32_t)((grow + b_n) * 128 + s * 32) + b_kb));
            mma16816h(c[2 * G], af[s], &bk[0]);
            mma16816h(c[2 * G + 1], af[s], &bk[2]);
        }
    }

    // ---- mask + ALiBi + exp2, row sums
    const int g = lane >> 2;
    const int tc2 = (lane & 3) * 2;
    float rs0 = 0.0f, rs1 = 0.0f;
#pragma unroll
    for (int jt = 0; jt < 18; jt++) {
        int nb = 16 * w + 8 * jt + tc2;           // global key-col for e=0
        int j0 = q0 - 128 + nb;                   // key index e=0 (e=1 -> j0+1)
        int d0 = g + 128 - 8 * jt - tc2;          // row g, e=0 (w cancels)
        int d1 = d0 - 1, d2 = d0 + 8, d3 = d0 + 7;
        float p0 = ex2(fmaf(c[jt][0], C1f, -(float)d0 * C2f));
        float p1 = ex2(fmaf(c[jt][1], C1f, -(float)d1 * C2f));
        float p2 = ex2(fmaf(c[jt][2], C1f, -(float)d2 * C2f));
        float p3 = ex2(fmaf(c[jt][3], C1f, -(float)d3 * C2f));
        p0 = (d0 >= 0 && d0 < WIN && j0 >= 0) ? p0 : 0.0f;
        p1 = (d1 >= 0 && d1 < WIN && j0 + 1 >= 0) ? p1 : 0.0f;
        p2 = (d2 >= 0 && d2 < WIN && j0 >= 0) ? p2 : 0.0f;
        p3 = (d3 >= 0 && d3 < WIN && j0 + 1 >= 0) ? p3 : 0.0f;
        c[jt][0] = p0; c[jt][1] = p1; c[jt][2] = p2; c[jt][3] = p3;
        rs0 += p0 + p1;
        rs1 += p2 + p3;
    }
    rs0 += __shfl_xor_sync(0xffffffffu, rs0, 1);
    rs1 += __shfl_xor_sync(0xffffffffu, rs1, 1);
    rs0 += __shfl_xor_sync(0xffffffffu, rs0, 2);
    rs1 += __shfl_xor_sync(0xffffffffu, rs1, 2);
    const float rinv0 = 1.0f / rs0;
    const float rinv1 = 1.0f / rs1;

    asm volatile("cp.async.wait_group 0;" ::: "memory");
    __syncthreads();

    // ---- PV: 3-term hi/lo over the 9 diagonal k16 steps
    float o[8][4];
#pragma unroll
    for (int j = 0; j < 8; j++)
#pragma unroll
        for (int k = 0; k < 4; k++) o[j][k] = 0.0f;

    const uint32_t vrow = (uint32_t)((lane & 7) + 8 * ((lane >> 3) & 1));
    const uint32_t vcb  = (uint32_t)(16 * (lane >> 4));

#pragma unroll
    for (int ss = 0; ss < 9; ss++) {
        const int s = w + ss;
        uint32_t aph[4], apl[4];
        aph[0] = h2pack(c[2 * ss][1], c[2 * ss][0]);
        aph[1] = h2pack(c[2 * ss][3], c[2 * ss][2]);
        aph[2] = h2pack(c[2 * ss + 1][1], c[2 * ss + 1][0]);
        aph[3] = h2pack(c[2 * ss + 1][3], c[2 * ss + 1][2]);
        {
            __half2 h0 = *reinterpret_cast<__half2*>(&aph[0]);
            __half2 h1 = *reinterpret_cast<__half2*>(&aph[1]);
            __half2 h2v = *reinterpret_cast<__half2*>(&aph[2]);
            __half2 h3 = *reinterpret_cast<__half2*>(&aph[3]);
            apl[0] = h2pack(c[2 * ss][1] - __high2float(h0),
                            c[2 * ss][0] - __low2float(h0));
            apl[1] = h2pack(c[2 * ss][3] - __high2float(h1),
                            c[2 * ss][2] - __low2float(h1));
            apl[2] = h2pack(c[2 * ss + 1][1] - __high2float(h2v),
                            c[2 * ss + 1][0] - __low2float(h2v));
            apl[3] = h2pack(c[2 * ss + 1][3] - __high2float(h3),
                            c[2 * ss + 1][2] - __low2float(h3));
        }
#pragma unroll
        for (int H = 0; H < 4; H++) {
            uint32_t ro = SW128((uint32_t)((16 * s + vrow) * 128 + 32 * H) + vcb);
            uint32_t vh[4], vl[4];
            ldsm_x4t(vh, sb + ATT_VH + ro);
            ldsm_x4t(vl, sb + ATT_VL + ro);
            mma16816h(o[2 * H], aph, &vh[0]);
            mma16816h(o[2 * H + 1], aph, &vh[2]);
            mma16816h(o[2 * H], aph, &vl[0]);
            mma16816h(o[2 * H + 1], aph, &vl[2]);
            mma16816h(o[2 * H], apl, &vh[0]);
            mma16816h(o[2 * H + 1], apl, &vh[2]);
        }
    }

    // ---- epilogue: normalize and store
    const int r0 = b * T_ + q0 + 16 * w + g;
#pragma unroll
    for (int j = 0; j < 8; j++) {
        *(float2*)(out + (size_t)r0 * HD + 8 * j + tc2) =
            make_float2(o[j][0] * rinv0, o[j][1] * rinv0);
        *(float2*)(out + (size_t)(r0 + 8) * HD + 8 * j + tc2) =
            make_float2(o[j][2] * rinv1, o[j][3] * rinv1);
    }
}

// ---------------------------------------------------------------------------
extern "C" void kernel_launch(void* const* d_in, const int* in_sizes, int n_in,
                              void* d_out, int out_size) {
    const float* x  = (const float*)d_in[0];
    const float* wq = (const float*)d_in[1];
    const float* wk = (const float*)d_in[2];
    const float* wv = (const float*)d_in[3];
    float* out = (float*)d_out;

    prep_w<<<192, 256>>>(wq, wk, wv);
    cudaFuncSetAttribute(qkv_mma_kernel,
                         cudaFuncAttributeMaxDynamicSharedMemorySize, QK_SMEM);
    qkv_mma_kernel<<<M_ / 128, 256, QK_SMEM>>>(x);
    cudaFuncSetAttribute(attn_kernel,
                         cudaFuncAttributeMaxDynamicSharedMemorySize, ATT_SMEM);
    attn_kernel<<<dim3(T_ / 64, B_), 128, ATT_SMEM>>>(out);
}

// round 9
// speedup vs baseline: 2.4797x; 1.0049x over previous
#include <cuda_runtime.h>
#include <cuda_fp16.h>
#include <cstdint>

// Problem constants
#define B_   4
#define T_   4096
#define C_   1024
#define HD   64
#define M_   (B_ * T_)      // 16384 rows
#define NW   192            // q(64) | k(64) | v(64) fused cols
#define WIN  128            // ALiBi window (exact to ~e^-89)

// Scratch: fused qkv as fp16 hi/lo planes [M_][192]
__device__ __align__(16) __half g_h[(size_t)M_ * NW];
__device__ __align__(16) __half g_l[(size_t)M_ * NW];
__device__ __align__(16) char g_wBh[16 * 24576];  // W fp16, per-chunk SW128 images

// ---------------- smem / mma helpers ----------------
__device__ __forceinline__ uint32_t smem_u32(const void* p) {
    uint32_t a;
    asm("{ .reg .u64 t; cvta.to.shared.u64 t, %1; cvt.u32.u64 %0, t; }"
        : "=r"(a) : "l"(p));
    return a;
}
#define SW128(off) ((off) ^ (((off) >> 3) & 0x70))

__device__ __forceinline__ void ldsm_x4(uint32_t* r, uint32_t addr) {
    asm volatile("ldmatrix.sync.aligned.m8n8.x4.shared.b16 {%0,%1,%2,%3}, [%4];"
                 : "=r"(r[0]), "=r"(r[1]), "=r"(r[2]), "=r"(r[3]) : "r"(addr));
}
__device__ __forceinline__ void ldsm_x4t(uint32_t* r, uint32_t addr) {
    asm volatile("ldmatrix.sync.aligned.m8n8.x4.trans.shared.b16 {%0,%1,%2,%3}, [%4];"
                 : "=r"(r[0]), "=r"(r[1]), "=r"(r[2]), "=r"(r[3]) : "r"(addr));
}
__device__ __forceinline__ void mma16816h(float* c, const uint32_t* a,
                                          const uint32_t* b) {
    asm volatile(
        "mma.sync.aligned.m16n8k16.row.col.f32.f16.f16.f32 "
        "{%0,%1,%2,%3}, {%4,%5,%6,%7}, {%8,%9}, {%0,%1,%2,%3};"
        : "+f"(c[0]), "+f"(c[1]), "+f"(c[2]), "+f"(c[3])
        : "r"(a[0]), "r"(a[1]), "r"(a[2]), "r"(a[3]), "r"(b[0]), "r"(b[1]));
}
__device__ __forceinline__ void cp_async16(uint32_t s, const void* g) {
    asm volatile("{ .reg .u64 gp; cvta.to.global.u64 gp, %1;"
                 " cp.async.cg.shared.global [%0], [gp], 16; }"
                 :: "r"(s), "l"(g) : "memory");
}
__device__ __forceinline__ uint32_t h2pack(float hi_f, float lo_f) {
    uint32_t r;   // r[15:0] = fp16(lo_f), r[31:16] = fp16(hi_f)
    asm("cvt.rn.f16x2.f32 %0, %1, %2;" : "=r"(r) : "f"(hi_f), "f"(lo_f));
    return r;
}
__device__ __forceinline__ float ex2(float x) {
    float r;
    asm("ex2.approx.ftz.f32 %0, %1;" : "=f"(r) : "f"(x));
    return r;
}

// ---------------------------------------------------------------------------
// Prep kernel: round W to fp16, stored as per-chunk SW128 images.
// ---------------------------------------------------------------------------
__global__ __launch_bounds__(256) void prep_w(const float* __restrict__ wq,
                                              const float* __restrict__ wk,
                                              const float* __restrict__ wv) {
    int idx = blockIdx.x * 256 + threadIdx.x;   // 0..49151
    int n = idx >> 8;
    int k4 = idx & 255;
    const float* wr = (n < 64)  ? (wq + (size_t)n * C_)
                    : (n < 128) ? (wk + (size_t)(n - 64) * C_)
                                : (wv + (size_t)(n - 128) * C_);
    float4 v = *(const float4*)(wr + k4 * 4);
    int k = k4 * 4;
    int ch = k >> 6, kk = k & 63;
    uint32_t sw = SW128((uint32_t)(n * 128 + kk * 2));
    uint2 hp;
    hp.x = h2pack(v.y, v.x);
    hp.y = h2pack(v.w, v.z);
    *(uint2*)(g_wBh + ch * 24576 + sw) = hp;
}

// ---------------------------------------------------------------------------
// Kernel 1: QKV projection via mma.sync fp16 (single-term W).
// BM=64, BN=192, BK=64, 256 threads, 8 warps = 2(M) x 4(N), warp tile 32x48.
// Grid 256 CTAs -> 2-3 CTAs/SM for DRAM MLP on the x stream.
// Double-buffered smem (32KB/buf): A fp16 @0 (8KB), Bh @8192 (24KB).
// ---------------------------------------------------------------------------
#define QK_BUF 32768
#define QK_SMEM (2 * QK_BUF)

__global__ __launch_bounds__(256) void qkv_mma_kernel(const float* __restrict__ x) {
    extern __shared__ char sm[];
    const uint32_t sb = smem_u32(sm);
    const int tid = threadIdx.x;
    const int wid = tid >> 5;
    const int lane = tid & 31;
    const int rowBase = blockIdx.x * 64;

    const int wm = (wid >> 2) * 32;   // warp M base (0 or 32)
    const int wn = (wid & 3) * 48;    // warp N base

    float acc[2][6][4];
#pragma unroll
    for (int i = 0; i < 2; i++)
#pragma unroll
        for (int j = 0; j < 6; j++)
#pragma unroll
            for (int k = 0; k < 4; k++) acc[i][j][k] = 0.0f;

    const uint32_t a_row = (uint32_t)(lane & 15);
    const uint32_t a_kb  = (uint32_t)((lane >> 4) * 16);
    const uint32_t b_n   = (uint32_t)((lane & 7) + ((lane >> 4) << 3));
    const uint32_t b_kb  = (uint32_t)(((lane >> 3) & 1) * 16);

    // A-load geometry: 64 rows x 8 c8-units = 512 units; 2 per thread
    const int ar0 = tid >> 3;          // + t*32
    const int ac8 = tid & 7;

    float4 av[4];

    // ---- prologue: chunk 0 ----
    {
#pragma unroll
        for (int t = 0; t < 6; t++)
            cp_async16(sb + 8192 + tid * 16 + t * 4096, g_wBh + tid * 16 + t * 4096);
        asm volatile("cp.async.commit_group;" ::: "memory");
#pragma unroll
        for (int t = 0; t < 2; t++) {
            const float* src = x + (size_t)(rowBase + ar0 + t * 32) * C_ + ac8 * 8;
            av[2 * t] = *(const float4*)src;
            av[2 * t + 1] = *(const float4*)(src + 4);
        }
#pragma unroll
        for (int t = 0; t < 2; t++) {
            uint4 p;
            p.x = h2pack(av[2 * t].y, av[2 * t].x);
            p.y = h2pack(av[2 * t].w, av[2 * t].z);
            p.z = h2pack(av[2 * t + 1].y, av[2 * t + 1].x);
            p.w = h2pack(av[2 * t + 1].w, av[2 * t + 1].z);
            uint32_t off = (uint32_t)((ar0 + t * 32) * 128 + ac8 * 16);
            *(uint4*)(sm + SW128(off)) = p;
        }
        asm volatile("cp.async.wait_group 0;" ::: "memory");
        __syncthreads();
    }

    for (int ch = 0; ch < 16; ch++) {
        const uint32_t cb = (uint32_t)(ch & 1) * QK_BUF;
        const uint32_t nb = (uint32_t)((ch + 1) & 1) * QK_BUF;
        const bool more = (ch < 15);

        if (more) {
            const char* gh = g_wBh + (ch + 1) * 24576;
#pragma unroll
            for (int t = 0; t < 6; t++)
                cp_async16(sb + nb + 8192 + tid * 16 + t * 4096, gh + tid * 16 + t * 4096);
            asm volatile("cp.async.commit_group;" ::: "memory");
            const int k0 = (ch + 1) * 64;
#pragma unroll
            for (int t = 0; t < 2; t++) {
                const float* src = x + (size_t)(rowBase + ar0 + t * 32) * C_ + k0 + ac8 * 8;
                av[2 * t] = *(const float4*)src;
                av[2 * t + 1] = *(const float4*)(src + 4);
            }
        }

#pragma unroll
        for (int s = 0; s < 4; s++) {
            const uint32_t ks16 = (uint32_t)(s * 32);
            uint32_t bh[3][4];
#pragma unroll
            for (int tn = 0; tn < 3; tn++) {
                uint32_t off = (uint32_t)((wn + tn * 16 + b_n) * 128) + ks16 + b_kb;
                ldsm_x4(bh[tn], sb + cb + 8192 + SW128(off));
            }
            uint32_t af[2][4];
#pragma unroll
            for (int tm = 0; tm < 2; tm++) {
                uint32_t off = (uint32_t)((wm + tm * 16 + a_row) * 128) + ks16 + a_kb;
                ldsm_x4(af[tm], sb + cb + SW128(off));
            }
#pragma unroll
            for (int tm = 0; tm < 2; tm++)
#pragma unroll
                for (int tn = 0; tn < 3; tn++) {
                    mma16816h(acc[tm][tn * 2 + 0], af[tm], &bh[tn][0]);
                    mma16816h(acc[tm][tn * 2 + 1], af[tm], &bh[tn][2]);
                }
        }

        if (more) {
#pragma unroll
            for (int t = 0; t < 2; t++) {
                uint4 p;
                p.x = h2pack(av[2 * t].y, av[2 * t].x);
                p.y = h2pack(av[2 * t].w, av[2 * t].z);
                p.z = h2pack(av[2 * t + 1].y, av[2 * t + 1].x);
                p.w = h2pack(av[2 * t + 1].w, av[2 * t + 1].z);
                uint32_t off = (uint32_t)((ar0 + t * 32) * 128 + ac8 * 16);
                *(uint4*)(sm + nb + SW128(off)) = p;
            }
            asm volatile("cp.async.wait_group 0;" ::: "memory");
        }
        __syncthreads();
    }

    // Epilogue: store fp16 hi + lo planes
    const int er = lane >> 2;
    const int ec = (lane & 3) * 2;
#pragma unroll
    for (int tm = 0; tm < 2; tm++) {
        int r0 = rowBase + wm + tm * 16 + er;
#pragma unroll
        for (int tn = 0; tn < 6; tn++) {
            int cc = wn + tn * 8 + ec;
            float a0 = acc[tm][tn][0], a1 = acc[tm][tn][1];
            float a2 = acc[tm][tn][2], a3 = acc[tm][tn][3];
            uint32_t h01 = h2pack(a1, a0);
            uint32_t h23 = h2pack(a3, a2);
            __half2 hh01 = *reinterpret_cast<__half2*>(&h01);
            __half2 hh23 = *reinterpret_cast<__half2*>(&h23);
            uint32_t l01 = h2pack(a1 - __high2float(hh01), a0 - __low2float(hh01));
            uint32_t l23 = h2pack(a3 - __high2float(hh23), a2 - __low2float(hh23));
            *(uint32_t*)(g_h + (size_t)r0 * NW + cc) = h01;
            *(uint32_t*)(g_l + (size_t)r0 * NW + cc) = l01;
            *(uint32_t*)(g_h + (size_t)(r0 + 8) * NW + cc) = h23;
            *(uint32_t*)(g_l + (size_t)(r0 + 8) * NW + cc) = l23;
        }
    }
}

// ---------------------------------------------------------------------------
// Kernel 2: banded tensor-core attention (unchanged from R6/R8).
// Block = 128 threads (4 warps) = 64 queries; key band [q0-128, q0+63].
// ---------------------------------------------------------------------------
#define ATT_Q  0
#define ATT_K  8192
#define ATT_VH 32768
#define ATT_VL 57344
#define ATT_SMEM 81920
#define C1f 0.045084246f      // (1/32) * log2(e)
#define C2f 1.0201941f        // slope * log2(e)

__global__ __launch_bounds__(128) void attn_kernel(float* __restrict__ out) {
    extern __shared__ char sm[];
    const uint32_t sb = smem_u32(sm);
    const int b = blockIdx.y;
    const int q0 = blockIdx.x * 64;
    const int tid = threadIdx.x;
    const int w = tid >> 5;
    const int lane = tid & 31;

#pragma unroll
    for (int t = 0; t < 16; t++) {
        int idx = tid + t * 128;
        const __half* src;
        uint32_t dst;
        if (idx < 512) {
            int qr = idx >> 3, c = idx & 7;
            src = g_h + (size_t)(b * T_ + q0 + qr) * NW + c * 8;
            dst = sb + ATT_Q + SW128((uint32_t)(qr * 128 + c * 16));
        } else {
            int i2 = idx - 512;
            int r = i2 >> 3, c = i2 & 7;
            int j = q0 - 128 + r;
            if (j < 0) j = 0;
            src = g_h + (size_t)(b * T_ + j) * NW + 64 + c * 8;
            dst = sb + ATT_K + SW128((uint32_t)(r * 128 + c * 16));
        }
        cp_async16(dst, src);
    }
    asm volatile("cp.async.commit_group;" ::: "memory");
#pragma unroll
    for (int t = 0; t < 24; t++) {
        int idx = tid + t * 128;
        int isL = (idx >= 1536);
        int i2 = isL ? idx - 1536 : idx;
        int r = i2 >> 3, c = i2 & 7;
        int j = q0 - 128 + r;
        if (j < 0) j = 0;
        const __half* src = (isL ? g_l : g_h) + (size_t)(b * T_ + j) * NW + 128 + c * 8;
        uint32_t dst = sb + (isL ? ATT_VL : ATT_VH) + SW128((uint32_t)(r * 128 + c * 16));
        cp_async16(dst, src);
    }
    asm volatile("cp.async.commit_group;" ::: "memory");
    asm volatile("cp.async.wait_group 1;" ::: "memory");
    __syncthreads();

    const uint32_t a_row = (uint32_t)(lane & 15);
    const uint32_t a_kb  = (uint32_t)((lane >> 4) * 16);
    const uint32_t b_n   = (uint32_t)((lane & 7) + ((lane >> 4) << 3));
    const uint32_t b_kb  = (uint32_t)(((lane >> 3) & 1) * 16);

    uint32_t af[4][4];
#pragma unroll
    for (int s = 0; s < 4; s++)
        ldsm_x4(af[s], sb + ATT_Q +
                SW128((uint32_t)((w * 16 + a_row) * 128 + s * 32) + a_kb));

    float c[18][4];
#pragma unroll
    for (int j = 0; j < 18; j++)
#pragma unroll
        for (int k = 0; k < 4; k++) c[j][k] = 0.0f;

#pragma unroll
    for (int G = 0; G < 9; G++) {
        const int grow = (w + G) * 16;
#pragma unroll
        for (int s = 0; s < 4; s++) {
            uint32_t bk[4];
            ldsm_x4(bk, sb + ATT_K +
                    SW128((uint32_t)((grow + b_n) * 128 + s * 32) + b_kb));
            mma16816h(c[2 * G], af[s], &bk[0]);
            mma16816h(c[2 * G + 1], af[s], &bk[2]);
        }
    }

    const int g = lane >> 2;
    const int tc2 = (lane & 3) * 2;
    float rs0 = 0.0f, rs1 = 0.0f;
#pragma unroll
    for (int jt = 0; jt < 18; jt++) {
        int nb = 16 * w + 8 * jt + tc2;
        int j0 = q0 - 128 + nb;
        int d0 = g + 128 - 8 * jt - tc2;
        int d1 = d0 - 1, d2 = d0 + 8, d3 = d0 + 7;
        float p0 = ex2(fmaf(c[jt][0], C1f, -(float)d0 * C2f));
        float p1 = ex2(fmaf(c[jt][1], C1f, -(float)d1 * C2f));
        float p2 = ex2(fmaf(c[jt][2], C1f, -(float)d2 * C2f));
        float p3 = ex2(fmaf(c[jt][3], C1f, -(float)d3 * C2f));
        p0 = (d0 >= 0 && d0 < WIN && j0 >= 0) ? p0 : 0.0f;
        p1 = (d1 >= 0 && d1 < WIN && j0 + 1 >= 0) ? p1 : 0.0f;
        p2 = (d2 >= 0 && d2 < WIN && j0 >= 0) ? p2 : 0.0f;
        p3 = (d3 >= 0 && d3 < WIN && j0 + 1 >= 0) ? p3 : 0.0f;
        c[jt][0] = p0; c[jt][1] = p1; c[jt][2] = p2; c[jt][3] = p3;
        rs0 += p0 + p1;
        rs1 += p2 + p3;
    }
    rs0 += __shfl_xor_sync(0xffffffffu, rs0, 1);
    rs1 += __shfl_xor_sync(0xffffffffu, rs1, 1);
    rs0 += __shfl_xor_sync(0xffffffffu, rs0, 2);
    rs1 += __shfl_xor_sync(0xffffffffu, rs1, 2);
    const float rinv0 = 1.0f / rs0;
    const float rinv1 = 1.0f / rs1;

    asm volatile("cp.async.wait_group 0;" ::: "memory");
    __syncthreads();

    float o[8][4];
#pragma unroll
    for (int j = 0; j < 8; j++)
#pragma unroll
        for (int k = 0; k < 4; k++) o[j][k] = 0.0f;

    const uint32_t vrow = (uint32_t)((lane & 7) + 8 * ((lane >> 3) & 1));
    const uint32_t vcb  = (uint32_t)(16 * (lane >> 4));

#pragma unroll
    for (int ss = 0; ss < 9; ss++) {
        const int s = w + ss;
        uint32_t aph[4], apl[4];
        aph[0] = h2pack(c[2 * ss][1], c[2 * ss][0]);
        aph[1] = h2pack(c[2 * ss][3], c[2 * ss][2]);
        aph[2] = h2pack(c[2 * ss + 1][1], c[2 * ss + 1][0]);
        aph[3] = h2pack(c[2 * ss + 1][3], c[2 * ss + 1][2]);
        {
            __half2 h0 = *reinterpret_cast<__half2*>(&aph[0]);
            __half2 h1 = *reinterpret_cast<__half2*>(&aph[1]);
            __half2 h2v = *reinterpret_cast<__half2*>(&aph[2]);
            __half2 h3 = *reinterpret_cast<__half2*>(&aph[3]);
            apl[0] = h2pack(c[2 * ss][1] - __high2float(h0),
                            c[2 * ss][0] - __low2float(h0));
            apl[1] = h2pack(c[2 * ss][3] - __high2float(h1),
                            c[2 * ss][2] - __low2float(h1));
            apl[2] = h2pack(c[2 * ss + 1][1] - __high2float(h2v),
                            c[2 * ss + 1][0] - __low2float(h2v));
            apl[3] = h2pack(c[2 * ss + 1][3] - __high2float(h3),
                            c[2 * ss + 1][2] - __low2float(h3));
        }
#pragma unroll
        for (int H = 0; H < 4; H++) {
            uint32_t ro = SW128((uint32_t)((16 * s + vrow) * 128 + 32 * H) + vcb);
            uint32_t vh[4], vl[4];
            ldsm_x4t(vh, sb + ATT_VH + ro);
            ldsm_x4t(vl, sb + ATT_VL + ro);
            mma16816h(o[2 * H], aph, &vh[0]);
            mma16816h(o[2 * H + 1], aph, &vh[2]);
            mma16816h(o[2 * H], aph, &vl[0]);
            mma16816h(o[2 * H + 1], aph, &vl[2]);
            mma16816h(o[2 * H], apl, &vh[0]);
            mma16816h(o[2 * H + 1], apl, &vh[2]);
        }
    }

    const int r0 = b * T_ + q0 + 16 * w + g;
#pragma unroll
    for (int j = 0; j < 8; j++) {
        *(float2*)(out + (size_t)r0 * HD + 8 * j + tc2) =
            make_float2(o[j][0] * rinv0, o[j][1] * rinv0);
        *(float2*)(out + (size_t)(r0 + 8) * HD + 8 * j + tc2) =
            make_float2(o[j][2] * rinv1, o[j][3] * rinv1);
    }
}

// ---------------------------------------------------------------------------
extern "C" void kernel_launch(void* const* d_in, const int* in_sizes, int n_in,
                              void* d_out, int out_size) {
    const float* x  = (const float*)d_in[0];
    const float* wq = (const float*)d_in[1];
    const float* wk = (const float*)d_in[2];
    const float* wv = (const float*)d_in[3];
    float* out = (float*)d_out;

    prep_w<<<192, 256>>>(wq, wk, wv);
    cudaFuncSetAttribute(qkv_mma_kernel,
                         cudaFuncAttributeMaxDynamicSharedMemorySize, QK_SMEM);
    qkv_mma_kernel<<<M_ / 64, 256, QK_SMEM>>>(x);
    cudaFuncSetAttribute(attn_kernel,
                         cudaFuncAttributeMaxDynamicSharedMemorySize, ATT_SMEM);
    attn_kernel<<<dim3(T_ / 64, B_), 128, ATT_SMEM>>>(out);
}

// round 11
// speedup vs baseline: 2.6542x; 1.0704x over previous
#include <cuda_runtime.h>
#include <cuda_fp16.h>
#include <cstdint>

// Problem constants
#define B_   4
#define T_   4096
#define C_   1024
#define HD   64
#define M_   (B_ * T_)      // 16384 rows
#define NW   192            // q(64) | k(64) | v(64) fused cols
#define WIN  128            // ALiBi window (exact to ~e^-89)

// Scratch: fused qkv fp16 [M_][192]
__device__ __align__(16) __half g_h[(size_t)M_ * NW];
__device__ __align__(16) char g_wBh[16 * 24576];  // W fp16, per-chunk SW128 images

// ---------------- smem / mma helpers ----------------
__device__ __forceinline__ uint32_t smem_u32(const void* p) {
    uint32_t a;
    asm("{ .reg .u64 t; cvta.to.shared.u64 t, %1; cvt.u32.u64 %0, t; }"
        : "=r"(a) : "l"(p));
    return a;
}
#define SW128(off) ((off) ^ (((off) >> 3) & 0x70))

__device__ __forceinline__ void ldsm_x4(uint32_t* r, uint32_t addr) {
    asm volatile("ldmatrix.sync.aligned.m8n8.x4.shared.b16 {%0,%1,%2,%3}, [%4];"
                 : "=r"(r[0]), "=r"(r[1]), "=r"(r[2]), "=r"(r[3]) : "r"(addr));
}
__device__ __forceinline__ void ldsm_x4t(uint32_t* r, uint32_t addr) {
    asm volatile("ldmatrix.sync.aligned.m8n8.x4.trans.shared.b16 {%0,%1,%2,%3}, [%4];"
                 : "=r"(r[0]), "=r"(r[1]), "=r"(r[2]), "=r"(r[3]) : "r"(addr));
}
__device__ __forceinline__ void mma16816h(float* c, const uint32_t* a,
                                          const uint32_t* b) {
    asm volatile(
        "mma.sync.aligned.m16n8k16.row.col.f32.f16.f16.f32 "
        "{%0,%1,%2,%3}, {%4,%5,%6,%7}, {%8,%9}, {%0,%1,%2,%3};"
        : "+f"(c[0]), "+f"(c[1]), "+f"(c[2]), "+f"(c[3])
        : "r"(a[0]), "r"(a[1]), "r"(a[2]), "r"(a[3]), "r"(b[0]), "r"(b[1]));
}
__device__ __forceinline__ void cp_async16(uint32_t s, const void* g) {
    asm volatile("{ .reg .u64 gp; cvta.to.global.u64 gp, %1;"
                 " cp.async.cg.shared.global [%0], [gp], 16; }"
                 :: "r"(s), "l"(g) : "memory");
}
__device__ __forceinline__ uint32_t h2pack(float hi_f, float lo_f) {
    uint32_t r;   // r[15:0] = fp16(lo_f), r[31:16] = fp16(hi_f)
    asm("cvt.rn.f16x2.f32 %0, %1, %2;" : "=r"(r) : "f"(hi_f), "f"(lo_f));
    return r;
}
__device__ __forceinline__ float ex2(float x) {
    float r;
    asm("ex2.approx.ftz.f32 %0, %1;" : "=f"(r) : "f"(x));
    return r;
}

// ---------------------------------------------------------------------------
// Prep kernel: round W to fp16, per-chunk SW128 images.
// 96 blocks x 256 threads; each thread: 8 consecutive k floats = 2 batched
// LDG.128 -> 1 STG.128 (swizzle preserves 16B blocks).
// ---------------------------------------------------------------------------
__global__ __launch_bounds__(256) void prep_w(const float* __restrict__ wq,
                                              const float* __restrict__ wk,
                                              const float* __restrict__ wv) {
    int idx = blockIdx.x * 256 + threadIdx.x;   // 0..24575
    int n = idx >> 7;
    int k = (idx & 127) * 8;
    const float* wr = (n < 64)  ? (wq + (size_t)n * C_)
                    : (n < 128) ? (wk + (size_t)(n - 64) * C_)
                                : (wv + (size_t)(n - 128) * C_);
    float4 v0 = *(const float4*)(wr + k);
    float4 v1 = *(const float4*)(wr + k + 4);
    int ch = k >> 6, koff = k & 63;
    uint4 p;
    p.x = h2pack(v0.y, v0.x);
    p.y = h2pack(v0.w, v0.z);
    p.z = h2pack(v1.y, v1.x);
    p.w = h2pack(v1.w, v1.z);
    *(uint4*)(g_wBh + ch * 24576 + SW128((uint32_t)(n * 128 + koff * 2))) = p;
}

// ---------------------------------------------------------------------------
// Kernel 1: QKV projection via mma.sync fp16 (single-term W).
// BM=64, BN=192, BK=64, 256 threads, 8 warps = 2(M) x 4(N), warp tile 32x48.
// Double-buffered smem (32KB/buf): A fp16 @0 (8KB), Bh @8192 (24KB).
// Epilogue stores single fp16 plane g_h.
// ---------------------------------------------------------------------------
#define QK_BUF 32768
#define QK_SMEM (2 * QK_BUF)

__global__ __launch_bounds__(256) void qkv_mma_kernel(const float* __restrict__ x) {
    extern __shared__ char sm[];
    const uint32_t sb = smem_u32(sm);
    const int tid = threadIdx.x;
    const int wid = tid >> 5;
    const int lane = tid & 31;
    const int rowBase = blockIdx.x * 64;

    const int wm = (wid >> 2) * 32;
    const int wn = (wid & 3) * 48;

    float acc[2][6][4];
#pragma unroll
    for (int i = 0; i < 2; i++)
#pragma unroll
        for (int j = 0; j < 6; j++)
#pragma unroll
            for (int k = 0; k < 4; k++) acc[i][j][k] = 0.0f;

    const uint32_t a_row = (uint32_t)(lane & 15);
    const uint32_t a_kb  = (uint32_t)((lane >> 4) * 16);
    const uint32_t b_n   = (uint32_t)((lane & 7) + ((lane >> 4) << 3));
    const uint32_t b_kb  = (uint32_t)(((lane >> 3) & 1) * 16);

    const int ar0 = tid >> 3;
    const int ac8 = tid & 7;

    float4 av[4];

    // ---- prologue: chunk 0 ----
    {
#pragma unroll
        for (int t = 0; t < 6; t++)
            cp_async16(sb + 8192 + tid * 16 + t * 4096, g_wBh + tid * 16 + t * 4096);
        asm volatile("cp.async.commit_group;" ::: "memory");
#pragma unroll
        for (int t = 0; t < 2; t++) {
            const float* src = x + (size_t)(rowBase + ar0 + t * 32) * C_ + ac8 * 8;
            av[2 * t] = *(const float4*)src;
            av[2 * t + 1] = *(const float4*)(src + 4);
        }
#pragma unroll
        for (int t = 0; t < 2; t++) {
            uint4 p;
            p.x = h2pack(av[2 * t].y, av[2 * t].x);
            p.y = h2pack(av[2 * t].w, av[2 * t].z);
            p.z = h2pack(av[2 * t + 1].y, av[2 * t + 1].x);
            p.w = h2pack(av[2 * t + 1].w, av[2 * t + 1].z);
            uint32_t off = (uint32_t)((ar0 + t * 32) * 128 + ac8 * 16);
            *(uint4*)(sm + SW128(off)) = p;
        }
        asm volatile("cp.async.wait_group 0;" ::: "memory");
        __syncthreads();
    }

    for (int ch = 0; ch < 16; ch++) {
        const uint32_t cb = (uint32_t)(ch & 1) * QK_BUF;
        const uint32_t nb = (uint32_t)((ch + 1) & 1) * QK_BUF;
        const bool more = (ch < 15);

        if (more) {
            const char* gh = g_wBh + (ch + 1) * 24576;
#pragma unroll
            for (int t = 0; t < 6; t++)
                cp_async16(sb + nb + 8192 + tid * 16 + t * 4096, gh + tid * 16 + t * 4096);
            asm volatile("cp.async.commit_group;" ::: "memory");
            const int k0 = (ch + 1) * 64;
#pragma unroll
            for (int t = 0; t < 2; t++) {
                const float* src = x + (size_t)(rowBase + ar0 + t * 32) * C_ + k0 + ac8 * 8;
                av[2 * t] = *(const float4*)src;
                av[2 * t + 1] = *(const float4*)(src + 4);
            }
        }

#pragma unroll
        for (int s = 0; s < 4; s++) {
            const uint32_t ks16 = (uint32_t)(s * 32);
            uint32_t bh[3][4];
#pragma unroll
            for (int tn = 0; tn < 3; tn++) {
                uint32_t off = (uint32_t)((wn + tn * 16 + b_n) * 128) + ks16 + b_kb;
                ldsm_x4(bh[tn], sb + cb + 8192 + SW128(off));
            }
            uint32_t af[2][4];
#pragma unroll
            for (int tm = 0; tm < 2; tm++) {
                uint32_t off = (uint32_t)((wm + tm * 16 + a_row) * 128) + ks16 + a_kb;
                ldsm_x4(af[tm], sb + cb + SW128(off));
            }
#pragma unroll
            for (int tm = 0; tm < 2; tm++)
#pragma unroll
                for (int tn = 0; tn < 3; tn++) {
                    mma16816h(acc[tm][tn * 2 + 0], af[tm], &bh[tn][0]);
                    mma16816h(acc[tm][tn * 2 + 1], af[tm], &bh[tn][2]);
                }
        }

        if (more) {
#pragma unroll
            for (int t = 0; t < 2; t++) {
                uint4 p;
                p.x = h2pack(av[2 * t].y, av[2 * t].x);
                p.y = h2pack(av[2 * t].w, av[2 * t].z);
                p.z = h2pack(av[2 * t + 1].y, av[2 * t + 1].x);
                p.w = h2pack(av[2 * t + 1].w, av[2 * t + 1].z);
                uint32_t off = (uint32_t)((ar0 + t * 32) * 128 + ac8 * 16);
                *(uint4*)(sm + nb + SW128(off)) = p;
            }
            asm volatile("cp.async.wait_group 0;" ::: "memory");
        }
        __syncthreads();
    }

    // Epilogue: store fp16 plane
    const int er = lane >> 2;
    const int ec = (lane & 3) * 2;
#pragma unroll
    for (int tm = 0; tm < 2; tm++) {
        int r0 = rowBase + wm + tm * 16 + er;
#pragma unroll
        for (int tn = 0; tn < 6; tn++) {
            int cc = wn + tn * 8 + ec;
            *(uint32_t*)(g_h + (size_t)r0 * NW + cc) =
                h2pack(acc[tm][tn][1], acc[tm][tn][0]);
            *(uint32_t*)(g_h + (size_t)(r0 + 8) * NW + cc) =
                h2pack(acc[tm][tn][3], acc[tm][tn][2]);
        }
    }
}

// ---------------------------------------------------------------------------
// Kernel 2: banded tensor-core attention, 1-term fp16 PV.
// Block = 128 threads (4 warps) = 64 queries; key band [q0-128, q0+63].
// Warp w: queries 16w..16w+15, diagonal k16 groups G = w..w+8.
// ---------------------------------------------------------------------------
#define ATT_Q  0
#define ATT_K  8192
#define ATT_VH 32768
#define ATT_SMEM 57344
#define C1f 0.045084246f      // (1/32) * log2(e)
#define C2f 1.0201941f        // slope * log2(e)

__global__ __launch_bounds__(128) void attn_kernel(float* __restrict__ out) {
    extern __shared__ char sm[];
    const uint32_t sb = smem_u32(sm);
    const int b = blockIdx.y;
    const int q0 = blockIdx.x * 64;
    const int tid = threadIdx.x;
    const int w = tid >> 5;
    const int lane = tid & 31;

    // ---- group A: Q (512 granules) + K (1536 granules)
#pragma unroll
    for (int t = 0; t < 16; t++) {
        int idx = tid + t * 128;
        const __half* src;
        uint32_t dst;
        if (idx < 512) {
            int qr = idx >> 3, c = idx & 7;
            src = g_h + (size_t)(b * T_ + q0 + qr) * NW + c * 8;
            dst = sb + ATT_Q + SW128((uint32_t)(qr * 128 + c * 16));
        } else {
            int i2 = idx - 512;
            int r = i2 >> 3, c = i2 & 7;
            int j = q0 - 128 + r;
            if (j < 0) j = 0;
            src = g_h + (size_t)(b * T_ + j) * NW + 64 + c * 8;
            dst = sb + ATT_K + SW128((uint32_t)(r * 128 + c * 16));
        }
        cp_async16(dst, src);
    }
    asm volatile("cp.async.commit_group;" ::: "memory");
    // ---- group B: V hi (1536 granules)
#pragma unroll
    for (int t = 0; t < 12; t++) {
        int idx = tid + t * 128;
        int r = idx >> 3, c = idx & 7;
        int j = q0 - 128 + r;
        if (j < 0) j = 0;
        const __half* src = g_h + (size_t)(b * T_ + j) * NW + 128 + c * 8;
        uint32_t dst = sb + ATT_VH + SW128((uint32_t)(r * 128 + c * 16));
        cp_async16(dst, src);
    }
    asm volatile("cp.async.commit_group;" ::: "memory");
    asm volatile("cp.async.wait_group 1;" ::: "memory");
    __syncthreads();

    const uint32_t a_row = (uint32_t)(lane & 15);
    const uint32_t a_kb  = (uint32_t)((lane >> 4) * 16);
    const uint32_t b_n   = (uint32_t)((lane & 7) + ((lane >> 4) << 3));
    const uint32_t b_kb  = (uint32_t)(((lane >> 3) & 1) * 16);

    uint32_t af[4][4];
#pragma unroll
    for (int s = 0; s < 4; s++)
        ldsm_x4(af[s], sb + ATT_Q +
                SW128((uint32_t)((w * 16 + a_row) * 128 + s * 32) + a_kb));

    float c[18][4];
#pragma unroll
    for (int j = 0; j < 18; j++)
#pragma unroll
        for (int k = 0; k < 4; k++) c[j][k] = 0.0f;

#pragma unroll
    for (int G = 0; G < 9; G++) {
        const int grow = (w + G) * 16;
#pragma unroll
        for (int s = 0; s < 4; s++) {
            uint32_t bk[4];
            ldsm_x4(bk, sb + ATT_K +
                    SW128((uint32_t)((grow + b_n) * 128 + s * 32) + b_kb));
            mma16816h(c[2 * G], af[s], &bk[0]);
            mma16816h(c[2 * G + 1], af[s], &bk[2]);
        }
    }

    // ---- mask + ALiBi + exp2, row sums
    const int g = lane >> 2;
    const int tc2 = (lane & 3) * 2;
    float rs0 = 0.0f, rs1 = 0.0f;
#pragma unroll
    for (int jt = 0; jt < 18; jt++) {
        int nb = 16 * w + 8 * jt + tc2;
        int j0 = q0 - 128 + nb;
        int d0 = g + 128 - 8 * jt - tc2;
        int d1 = d0 - 1, d2 = d0 + 8, d3 = d0 + 7;
        float p0 = ex2(fmaf(c[jt][0], C1f, -(float)d0 * C2f));
        float p1 = ex2(fmaf(c[jt][1], C1f, -(float)d1 * C2f));
        float p2 = ex2(fmaf(c[jt][2], C1f, -(float)d2 * C2f));
        float p3 = ex2(fmaf(c[jt][3], C1f, -(float)d3 * C2f));
        p0 = (d0 >= 0 && d0 < WIN && j0 >= 0) ? p0 : 0.0f;
        p1 = (d1 >= 0 && d1 < WIN && j0 + 1 >= 0) ? p1 : 0.0f;
        p2 = (d2 >= 0 && d2 < WIN && j0 >= 0) ? p2 : 0.0f;
        p3 = (d3 >= 0 && d3 < WIN && j0 + 1 >= 0) ? p3 : 0.0f;
        c[jt][0] = p0; c[jt][1] = p1; c[jt][2] = p2; c[jt][3] = p3;
        rs0 += p0 + p1;
        rs1 += p2 + p3;
    }
    rs0 += __shfl_xor_sync(0xffffffffu, rs0, 1);
    rs1 += __shfl_xor_sync(0xffffffffu, rs1, 1);
    rs0 += __shfl_xor_sync(0xffffffffu, rs0, 2);
    rs1 += __shfl_xor_sync(0xffffffffu, rs1, 2);
    const float rinv0 = 1.0f / rs0;
    const float rinv1 = 1.0f / rs1;

    asm volatile("cp.async.wait_group 0;" ::: "memory");
    __syncthreads();

    // ---- PV: single-term fp16
    float o[8][4];
#pragma unroll
    for (int j = 0; j < 8; j++)
#pragma unroll
        for (int k = 0; k < 4; k++) o[j][k] = 0.0f;

    const uint32_t vrow = (uint32_t)((lane & 7) + 8 * ((lane >> 3) & 1));
    const uint32_t vcb  = (uint32_t)(16 * (lane >> 4));

#pragma unroll
    for (int ss = 0; ss < 9; ss++) {
        const int s = w + ss;
        uint32_t aph[4];
        aph[0] = h2pack(c[2 * ss][1], c[2 * ss][0]);
        aph[1] = h2pack(c[2 * ss][3], c[2 * ss][2]);
        aph[2] = h2pack(c[2 * ss + 1][1], c[2 * ss + 1][0]);
        aph[3] = h2pack(c[2 * ss + 1][3], c[2 * ss + 1][2]);
#pragma unroll
        for (int H = 0; H < 4; H++) {
            uint32_t ro = SW128((uint32_t)((16 * s + vrow) * 128 + 32 * H) + vcb);
            uint32_t vh[4];
            ldsm_x4t(vh, sb + ATT_VH + ro);
            mma16816h(o[2 * H], aph, &vh[0]);
            mma16816h(o[2 * H + 1], aph, &vh[2]);
        }
    }

    // ---- epilogue: normalize and store
    const int r0 = b * T_ + q0 + 16 * w + g;
#pragma unroll
    for (int j = 0; j < 8; j++) {
        *(float2*)(out + (size_t)r0 * HD + 8 * j + tc2) =
            make_float2(o[j][0] * rinv0, o[j][1] * rinv0);
        *(float2*)(out + (size_t)(r0 + 8) * HD + 8 * j + tc2) =
            make_float2(o[j][2] * rinv1, o[j][3] * rinv1);
    }
}

// ---------------------------------------------------------------------------
extern "C" void kernel_launch(void* const* d_in, const int* in_sizes, int n_in,
                              void* d_out, int out_size) {
    const float* x  = (const float*)d_in[0];
    const float* wq = (const float*)d_in[1];
    const float* wk = (const float*)d_in[2];
    const float* wv = (const float*)d_in[3];
    float* out = (float*)d_out;

    prep_w<<<96, 256>>>(wq, wk, wv);
    cudaFuncSetAttribute(qkv_mma_kernel,
                         cudaFuncAttributeMaxDynamicSharedMemorySize, QK_SMEM);
    qkv_mma_kernel<<<M_ / 64, 256, QK_SMEM>>>(x);
    cudaFuncSetAttribute(attn_kernel,
                         cudaFuncAttributeMaxDynamicSharedMemorySize, ATT_SMEM);
    attn_kernel<<<dim3(T_ / 64, B_), 128, ATT_SMEM>>>(out);
}